// round 1
// baseline (speedup 1.0000x reference)
#include <cuda_runtime.h>
#include <math.h>

// Problem constants
#define BB    32
#define TT    512
#define DIMV  512
#define QQ    8
#define CC    256
#define DD    256
#define HIDV  1024
#define MROWS (BB*TT)          // 16384
#define XR_N  (MROWS*DIMV)     // 8388608
#define IDX_N (MROWS*QQ)       // 131072

// ---------------- scratch (static device globals; no runtime alloc) ----------------
__device__ float g_xt [MROWS*DIMV];     // transposed input / loss reference
__device__ float g_h0 [MROWS*HIDV];
__device__ float g_h1 [MROWS*HIDV];
__device__ float g_z  [MROWS*QQ*DD];
__device__ float g_emb[MROWS*DD];
__device__ int   g_code[MROWS*QQ];
__device__ float g_sum[2048];
__device__ float g_sumsq[2048];
__device__ float g_scale[2048];
__device__ float g_shift[2048];
__device__ float g_loss[1];

// ---------------- transpose: x[b, d, t] -> xt[b*T+t, d] ----------------
__global__ void transpose_kernel(const float* __restrict__ x, float* __restrict__ xt) {
    __shared__ float tile[32][33];
    int b  = blockIdx.z;
    int t0 = blockIdx.x * 32;
    int d0 = blockIdx.y * 32;
    int tx = threadIdx.x, ty = threadIdx.y;
    const float* xb = x  + (size_t)b * DIMV * TT;
    float*      xtb = xt + (size_t)b * TT * DIMV;
#pragma unroll
    for (int j = 0; j < 32; j += 8)
        tile[ty + j][tx] = xb[(size_t)(d0 + ty + j) * TT + t0 + tx];
    __syncthreads();
#pragma unroll
    for (int j = 0; j < 32; j += 8)
        xtb[(size_t)(t0 + ty + j) * DIMV + d0 + tx] = tile[tx][ty + j];
}

// ---------------- fp32 GEMM: C[M,N] = A[M,K] @ W[N,K]^T + bias ----------------
// 128x128 tile, BK=16, 256 threads, 8x8 per-thread. Optional fused MSE-loss
// epilogue (ref != nullptr): accumulates sum((C - ref)^2) into lossAcc.
__global__ __launch_bounds__(256) void gemm128(
    const float* __restrict__ A, const float* __restrict__ W,
    const float* __restrict__ bias, float* __restrict__ C,
    int M, int N, int K,
    const float* __restrict__ ref, float* __restrict__ lossAcc)
{
    __shared__ float As[16][128];
    __shared__ float Ws[16][128];
    __shared__ float red[8];
    const int tid = threadIdx.x;
    const int m0  = blockIdx.y * 128;
    const int n0  = blockIdx.x * 128;
    const int tm  = tid >> 4;
    const int tn  = tid & 15;

    float acc[8][8];
#pragma unroll
    for (int i = 0; i < 8; i++)
#pragma unroll
        for (int j = 0; j < 8; j++) acc[i][j] = 0.f;

    for (int k0 = 0; k0 < K; k0 += 16) {
#pragma unroll
        for (int i = 0; i < 2; i++) {
            int idx = tid + i * 256;          // 0..511 -> 128 rows x 4 float4
            int row = idx >> 2;
            int kq  = (idx & 3) << 2;
            float4 av = *(const float4*)(A + (size_t)(m0 + row) * K + k0 + kq);
            As[kq + 0][row] = av.x; As[kq + 1][row] = av.y;
            As[kq + 2][row] = av.z; As[kq + 3][row] = av.w;
            float4 wv = *(const float4*)(W + (size_t)(n0 + row) * K + k0 + kq);
            Ws[kq + 0][row] = wv.x; Ws[kq + 1][row] = wv.y;
            Ws[kq + 2][row] = wv.z; Ws[kq + 3][row] = wv.w;
        }
        __syncthreads();
#pragma unroll
        for (int k = 0; k < 16; k++) {
            float a[8], b[8];
            *(float4*)&a[0] = *(const float4*)&As[k][tm * 8];
            *(float4*)&a[4] = *(const float4*)&As[k][tm * 8 + 4];
            *(float4*)&b[0] = *(const float4*)&Ws[k][tn * 8];
            *(float4*)&b[4] = *(const float4*)&Ws[k][tn * 8 + 4];
#pragma unroll
            for (int i = 0; i < 8; i++)
#pragma unroll
                for (int j = 0; j < 8; j++) acc[i][j] += a[i] * b[j];
        }
        __syncthreads();
    }

    float lsum = 0.f;
#pragma unroll
    for (int i = 0; i < 8; i++) {
        int m = m0 + tm * 8 + i;
#pragma unroll
        for (int j = 0; j < 8; j++) {
            int n = n0 + tn * 8 + j;
            float v = acc[i][j] + bias[n];
            C[(size_t)m * N + n] = v;
            if (ref) { float d = v - ref[(size_t)m * N + n]; lsum += d * d; }
        }
    }
    if (lossAcc) {
#pragma unroll
        for (int off = 16; off; off >>= 1)
            lsum += __shfl_down_sync(0xffffffffu, lsum, off);
        if ((tid & 31) == 0) red[tid >> 5] = lsum;
        __syncthreads();
        if (tid == 0) {
            float s = 0.f;
            for (int w = 0; w < 8; w++) s += red[w];
            atomicAdd(lossAcc, s);
        }
    }
}

// ---------------- BN: per-column sum / sumsq over M=16384 rows ----------------
__global__ void colstats_kernel(const float* __restrict__ X, int N,
                                float* __restrict__ sum, float* __restrict__ sumsq) {
    int col = blockIdx.x * 32 + threadIdx.x;
    int r0  = blockIdx.y * 2048;
    float s = 0.f, ss = 0.f;
    for (int r = r0 + threadIdx.y; r < r0 + 2048; r += 8) {
        float v = X[(size_t)r * N + col];
        s += v; ss += v * v;
    }
    __shared__ float sh [8][32];
    __shared__ float sh2[8][32];
    sh [threadIdx.y][threadIdx.x] = s;
    sh2[threadIdx.y][threadIdx.x] = ss;
    __syncthreads();
    if (threadIdx.y == 0) {
#pragma unroll
        for (int w = 1; w < 8; w++) { s += sh[w][threadIdx.x]; ss += sh2[w][threadIdx.x]; }
        atomicAdd(&sum[col], s);
        atomicAdd(&sumsq[col], ss);
    }
}

__global__ void bnparams_kernel(const float* __restrict__ sum, const float* __restrict__ sumsq,
                                const float* __restrict__ g, const float* __restrict__ be, int N) {
    int c = blockIdx.x * 128 + threadIdx.x;
    if (c >= N) return;
    const float invM = 1.0f / (float)MROWS;
    float m   = sum[c] * invM;
    float var = sumsq[c] * invM - m * m;     // biased var, matches reference
    float sc  = g[c] * rsqrtf(var + 1e-5f);
    g_scale[c] = sc;
    g_shift[c] = be[c] - m * sc;
}

__global__ void bnapply_kernel(float* __restrict__ X, int mask, int relu) {
    size_t i = (size_t)blockIdx.x * 256 + threadIdx.x;
    int c = (int)i & mask;
    float v = X[i] * g_scale[c] + g_shift[c];
    if (relu) v = fmaxf(v, 0.f);
    X[i] = v;
}

// ---------------- logits + dual argmax (fused) ----------------
// Block: 64 rows x one codebook q; 256 threads (thread = code c).
// Computes logits_raw[r,c] = dot(z[r,q,:], codebook[q,c,:]) with smem-staged z,
// then per-row argmax of raw (-> indices) and of raw*exp(-lt)+gumbel (-> code).
__global__ __launch_bounds__(256) void logits_argmax_kernel(
    const float* __restrict__ Z, const float* __restrict__ cb,
    const float* __restrict__ u, const float* __restrict__ lt,
    float* __restrict__ idx_out, int* __restrict__ code_out)
{
    extern __shared__ float sm[];
    float* zs = sm;                 // [32][64]  k-major z tile
    float* gs = sm + 32 * 64;       // [64][256] gumbel noise
    float* ls = gs + 64 * 256;      // [64][256] raw logits
    __shared__ float swv[8], swnv[8];
    __shared__ int   swi[8], swni[8];

    const int tid = threadIdx.x;
    const int q   = blockIdx.y;
    const int r0  = blockIdx.x * 64;
    const float scale = expf(-lt[q]);

    // Gumbel tile: each thread writes (and later reads) column c = tid only.
    for (int i = tid; i < 64 * 256; i += 256) {
        int r = i >> 8;
        float uu = u[((size_t)(r0 + r) * QQ + q) * CC + tid];
        uu = fminf(fmaxf(uu, 1e-9f), 1.0f);
        gs[i] = -logf(-logf(uu) + 1e-20f);
    }

    float acc[64];
#pragma unroll
    for (int r = 0; r < 64; r++) acc[r] = 0.f;

    const float* cbrow = cb + ((size_t)q * CC + tid) * DD;

    for (int kc = 0; kc < 256; kc += 32) {
        __syncthreads();
#pragma unroll
        for (int i = 0; i < 2; i++) {
            int idx = tid + i * 256;    // 0..511 -> 64 rows x 8 float4
            int r  = idx >> 3;
            int k4 = (idx & 7) << 2;
            float4 v = *(const float4*)(Z + (size_t)(r0 + r) * (QQ * DD) + q * DD + kc + k4);
            zs[(k4 + 0) * 64 + r] = v.x; zs[(k4 + 1) * 64 + r] = v.y;
            zs[(k4 + 2) * 64 + r] = v.z; zs[(k4 + 3) * 64 + r] = v.w;
        }
        __syncthreads();
#pragma unroll
        for (int k4 = 0; k4 < 8; k4++) {
            float4 w4 = *(const float4*)(cbrow + kc + k4 * 4);
            float wv[4] = {w4.x, w4.y, w4.z, w4.w};
#pragma unroll
            for (int kk = 0; kk < 4; kk++) {
                const float* zrow = zs + (k4 * 4 + kk) * 64;
                float w = wv[kk];
#pragma unroll
                for (int r4 = 0; r4 < 16; r4++) {
                    float4 z4 = *(const float4*)(zrow + r4 * 4);
                    acc[r4 * 4 + 0] += z4.x * w;
                    acc[r4 * 4 + 1] += z4.y * w;
                    acc[r4 * 4 + 2] += z4.z * w;
                    acc[r4 * 4 + 3] += z4.w * w;
                }
            }
        }
    }
    // Spill logits to smem so the (non-unrolled) reduction loop can index by r.
#pragma unroll
    for (int r = 0; r < 64; r++) ls[r * 256 + tid] = acc[r];
    __syncthreads();

    const int lane = tid & 31, wid = tid >> 5;
    for (int r = 0; r < 64; r++) {
        float rv = ls[r * 256 + tid]; int ri = tid;
        float nv = rv * scale + gs[r * 256 + tid]; int ni = tid;
#pragma unroll
        for (int off = 16; off; off >>= 1) {
            float orv = __shfl_down_sync(0xffffffffu, rv, off);
            int   ori = __shfl_down_sync(0xffffffffu, ri, off);
            float onv = __shfl_down_sync(0xffffffffu, nv, off);
            int   oni = __shfl_down_sync(0xffffffffu, ni, off);
            if (orv > rv || (orv == rv && ori < ri)) { rv = orv; ri = ori; }
            if (onv > nv || (onv == nv && oni < ni)) { nv = onv; ni = oni; }
        }
        if (lane == 0) { swv[wid] = rv; swi[wid] = ri; swnv[wid] = nv; swni[wid] = ni; }
        __syncthreads();
        if (tid == 0) {
            float brv = swv[0];  int bri = swi[0];
            float bnv = swnv[0]; int bni = swni[0];
#pragma unroll
            for (int w = 1; w < 8; w++) {
                if (swv[w]  > brv || (swv[w]  == brv && swi[w]  < bri)) { brv = swv[w];  bri = swi[w]; }
                if (swnv[w] > bnv || (swnv[w] == bnv && swni[w] < bni)) { bnv = swnv[w]; bni = swni[w]; }
            }
            size_t o = (size_t)(r0 + r) * QQ + q;
            idx_out[o]  = (float)bri;   // indices = argmax(logits_raw)
            code_out[o] = bni;          // argmax(logits*e^{-t} + gumbel) == argmax(y_soft)
        }
        __syncthreads();
    }
}

// ---------------- embedding gather: emb[bt,:] = sum_q codebook[q, code[bt,q], :] ----
__global__ void embed_kernel(const int* __restrict__ code, const float* __restrict__ cb,
                             float* __restrict__ emb) {
    int bt = blockIdx.x;
    int d  = threadIdx.x;
    float s = 0.f;
#pragma unroll
    for (int q = 0; q < QQ; q++) {
        int ci = code[bt * QQ + q];
        s += cb[((size_t)(q * CC + ci)) * DD + d];
    }
    emb[(size_t)bt * DD + d] = s;
}

__global__ void finalize_loss_kernel(float* __restrict__ out) {
    out[0] = g_loss[0] * (1.0f / (float)XR_N);
}

// ---------------- host orchestration ----------------
extern "C" void kernel_launch(void* const* d_in, const int* in_sizes, int n_in,
                              void* d_out, int out_size) {
    const float* x       = (const float*)d_in[0];
    const float* u       = (const float*)d_in[1];
    const float* cb      = (const float*)d_in[2];
    const float* lt      = (const float*)d_in[3];
    const float* enc_w0  = (const float*)d_in[4];
    const float* enc_b0  = (const float*)d_in[5];
    const float* enc_g0  = (const float*)d_in[6];
    const float* enc_be0 = (const float*)d_in[7];
    const float* enc_w1  = (const float*)d_in[8];
    const float* enc_b1  = (const float*)d_in[9];
    const float* enc_g1  = (const float*)d_in[10];
    const float* enc_be1 = (const float*)d_in[11];
    const float* enc_wo  = (const float*)d_in[12];
    const float* enc_bo  = (const float*)d_in[13];
    const float* dec_g   = (const float*)d_in[14];
    const float* dec_be  = (const float*)d_in[15];
    const float* dec_w0  = (const float*)d_in[16];
    const float* dec_b0  = (const float*)d_in[17];
    const float* dec_g0  = (const float*)d_in[18];
    const float* dec_be0 = (const float*)d_in[19];
    const float* dec_w1  = (const float*)d_in[20];
    const float* dec_b1  = (const float*)d_in[21];
    const float* dec_g1  = (const float*)d_in[22];
    const float* dec_be1 = (const float*)d_in[23];
    const float* fin_w   = (const float*)d_in[24];
    const float* fin_b   = (const float*)d_in[25];
    float* out = (float*)d_out;

    float *xt, *h0, *h1, *z, *emb, *sum, *sumsq, *loss;
    int* code;
    cudaGetSymbolAddress((void**)&xt,   g_xt);
    cudaGetSymbolAddress((void**)&h0,   g_h0);
    cudaGetSymbolAddress((void**)&h1,   g_h1);
    cudaGetSymbolAddress((void**)&z,    g_z);
    cudaGetSymbolAddress((void**)&emb,  g_emb);
    cudaGetSymbolAddress((void**)&code, g_code);
    cudaGetSymbolAddress((void**)&sum,  g_sum);
    cudaGetSymbolAddress((void**)&sumsq,g_sumsq);
    cudaGetSymbolAddress((void**)&loss, g_loss);

    cudaFuncSetAttribute(logits_argmax_kernel,
                         cudaFuncAttributeMaxDynamicSharedMemorySize, 139264);

    auto run_bn = [&](float* X, int N, const float* g, const float* be, int relu) {
        cudaMemsetAsync(sum,   0, N * sizeof(float));
        cudaMemsetAsync(sumsq, 0, N * sizeof(float));
        colstats_kernel<<<dim3(N / 32, 8), dim3(32, 8)>>>(X, N, sum, sumsq);
        bnparams_kernel<<<(N + 127) / 128, 128>>>(sum, sumsq, g, be, N);
        bnapply_kernel<<<(unsigned)(((size_t)MROWS * N) / 256), 256>>>(X, N - 1, relu);
    };

    // encoder
    transpose_kernel<<<dim3(TT / 32, DIMV / 32, BB), dim3(32, 8)>>>(x, xt);
    gemm128<<<dim3(HIDV / 128, MROWS / 128), 256>>>(xt, enc_w0, enc_b0, h0,
                                                    MROWS, HIDV, DIMV, nullptr, nullptr);
    run_bn(h0, HIDV, enc_g0, enc_be0, 1);
    gemm128<<<dim3(HIDV / 128, MROWS / 128), 256>>>(h0, enc_w1, enc_b1, h1,
                                                    MROWS, HIDV, HIDV, nullptr, nullptr);
    run_bn(h1, HIDV, enc_g1, enc_be1, 1);
    gemm128<<<dim3((QQ * DD) / 128, MROWS / 128), 256>>>(h1, enc_wo, enc_bo, z,
                                                         MROWS, QQ * DD, HIDV, nullptr, nullptr);

    // quantization: logits + dual argmax, then codebook gather
    logits_argmax_kernel<<<dim3(MROWS / 64, QQ), 256, 139264>>>(z, cb, u, lt,
                                                                out + XR_N, code);
    embed_kernel<<<MROWS, DD>>>(code, cb, emb);

    // decoder
    run_bn(emb, DD, dec_g, dec_be, 0);
    gemm128<<<dim3(HIDV / 128, MROWS / 128), 256>>>(emb, dec_w0, dec_b0, h0,
                                                    MROWS, HIDV, DD, nullptr, nullptr);
    run_bn(h0, HIDV, dec_g0, dec_be0, 1);
    gemm128<<<dim3(HIDV / 128, MROWS / 128), 256>>>(h0, dec_w1, dec_b1, h1,
                                                    MROWS, HIDV, HIDV, nullptr, nullptr);
    run_bn(h1, HIDV, dec_g1, dec_be1, 1);

    // final linear, fused with x_reco store + MSE loss vs xt
    cudaMemsetAsync(loss, 0, sizeof(float));
    gemm128<<<dim3(DIMV / 128, MROWS / 128), 256>>>(h1, fin_w, fin_b, out,
                                                    MROWS, DIMV, HIDV, xt, loss);
    finalize_loss_kernel<<<1, 1>>>(out + XR_N + IDX_N);
}

// round 5
// speedup vs baseline: 1.0579x; 1.0579x over previous
#include <cuda_runtime.h>
#include <math.h>
#include <stdint.h>

// Problem constants
#define BB    32
#define TT    512
#define DIMV  512
#define QQ    8
#define CC    256
#define DD    256
#define HIDV  1024
#define MROWS (BB*TT)          // 16384
#define XR_N  (MROWS*DIMV)     // 8388608
#define IDX_N (MROWS*QQ)       // 131072

// ---------------- scratch (static device globals; no runtime alloc) ----------------
__device__ float g_xt [MROWS*DIMV];
__device__ float g_h0 [MROWS*HIDV];
__device__ float g_h1 [MROWS*HIDV];
__device__ float g_z  [MROWS*QQ*DD];
__device__ float g_emb[MROWS*DD];
__device__ int   g_code[MROWS*QQ];
__device__ float g_sum[2048];
__device__ float g_sumsq[2048];
__device__ float g_scale[2048];
__device__ float g_shift[2048];
__device__ float g_loss[1];

// ======================================================================
// ===== R0-exact path (encoder + logits/argmax): DO NOT CHANGE ARITH ===
// ======================================================================

// ---------------- transpose: x[b, d, t] -> xt[b*T+t, d] ----------------
__global__ void transpose_kernel(const float* __restrict__ x, float* __restrict__ xt) {
    __shared__ float tile[32][33];
    int b  = blockIdx.z;
    int t0 = blockIdx.x * 32;
    int d0 = blockIdx.y * 32;
    int tx = threadIdx.x, ty = threadIdx.y;
    const float* xb = x  + (size_t)b * DIMV * TT;
    float*      xtb = xt + (size_t)b * TT * DIMV;
#pragma unroll
    for (int j = 0; j < 32; j += 8)
        tile[ty + j][tx] = xb[(size_t)(d0 + ty + j) * TT + t0 + tx];
    __syncthreads();
#pragma unroll
    for (int j = 0; j < 32; j += 8)
        xtb[(size_t)(t0 + ty + j) * DIMV + d0 + tx] = tile[tx][ty + j];
}

// ---------------- fp32 SIMT GEMM (R0 verbatim): C = A @ W^T + bias ----------------
__global__ __launch_bounds__(256) void gemm128(
    const float* __restrict__ A, const float* __restrict__ W,
    const float* __restrict__ bias, float* __restrict__ C,
    int M, int N, int K,
    const float* __restrict__ ref, float* __restrict__ lossAcc)
{
    __shared__ float As[16][128];
    __shared__ float Ws[16][128];
    __shared__ float red[8];
    const int tid = threadIdx.x;
    const int m0  = blockIdx.y * 128;
    const int n0  = blockIdx.x * 128;
    const int tm  = tid >> 4;
    const int tn  = tid & 15;

    float acc[8][8];
#pragma unroll
    for (int i = 0; i < 8; i++)
#pragma unroll
        for (int j = 0; j < 8; j++) acc[i][j] = 0.f;

    for (int k0 = 0; k0 < K; k0 += 16) {
#pragma unroll
        for (int i = 0; i < 2; i++) {
            int idx = tid + i * 256;
            int row = idx >> 2;
            int kq  = (idx & 3) << 2;
            float4 av = *(const float4*)(A + (size_t)(m0 + row) * K + k0 + kq);
            As[kq + 0][row] = av.x; As[kq + 1][row] = av.y;
            As[kq + 2][row] = av.z; As[kq + 3][row] = av.w;
            float4 wv = *(const float4*)(W + (size_t)(n0 + row) * K + k0 + kq);
            Ws[kq + 0][row] = wv.x; Ws[kq + 1][row] = wv.y;
            Ws[kq + 2][row] = wv.z; Ws[kq + 3][row] = wv.w;
        }
        __syncthreads();
#pragma unroll
        for (int k = 0; k < 16; k++) {
            float a[8], b[8];
            *(float4*)&a[0] = *(const float4*)&As[k][tm * 8];
            *(float4*)&a[4] = *(const float4*)&As[k][tm * 8 + 4];
            *(float4*)&b[0] = *(const float4*)&Ws[k][tn * 8];
            *(float4*)&b[4] = *(const float4*)&Ws[k][tn * 8 + 4];
#pragma unroll
            for (int i = 0; i < 8; i++)
#pragma unroll
                for (int j = 0; j < 8; j++) acc[i][j] += a[i] * b[j];
        }
        __syncthreads();
    }

    float lsum = 0.f;
#pragma unroll
    for (int i = 0; i < 8; i++) {
        int m = m0 + tm * 8 + i;
#pragma unroll
        for (int j = 0; j < 8; j++) {
            int n = n0 + tn * 8 + j;
            float v = acc[i][j] + bias[n];
            C[(size_t)m * N + n] = v;
            if (ref) { float d = v - ref[(size_t)m * N + n]; lsum += d * d; }
        }
    }
    if (lossAcc) {
#pragma unroll
        for (int off = 16; off; off >>= 1)
            lsum += __shfl_down_sync(0xffffffffu, lsum, off);
        if ((tid & 31) == 0) red[tid >> 5] = lsum;
        __syncthreads();
        if (tid == 0) {
            float s = 0.f;
            for (int w = 0; w < 8; w++) s += red[w];
            atomicAdd(lossAcc, s);
        }
    }
}

// ---------------- BN kernels (R0 verbatim) ----------------
__global__ void colstats_kernel(const float* __restrict__ X, int N,
                                float* __restrict__ sum, float* __restrict__ sumsq) {
    int col = blockIdx.x * 32 + threadIdx.x;
    int r0  = blockIdx.y * 2048;
    float s = 0.f, ss = 0.f;
    for (int r = r0 + threadIdx.y; r < r0 + 2048; r += 8) {
        float v = X[(size_t)r * N + col];
        s += v; ss += v * v;
    }
    __shared__ float sh [8][32];
    __shared__ float sh2[8][32];
    sh [threadIdx.y][threadIdx.x] = s;
    sh2[threadIdx.y][threadIdx.x] = ss;
    __syncthreads();
    if (threadIdx.y == 0) {
#pragma unroll
        for (int w = 1; w < 8; w++) { s += sh[w][threadIdx.x]; ss += sh2[w][threadIdx.x]; }
        atomicAdd(&sum[col], s);
        atomicAdd(&sumsq[col], ss);
    }
}

__global__ void bnparams_kernel(const float* __restrict__ sum, const float* __restrict__ sumsq,
                                const float* __restrict__ g, const float* __restrict__ be, int N) {
    int c = blockIdx.x * 128 + threadIdx.x;
    if (c >= N) return;
    const float invM = 1.0f / (float)MROWS;
    float m   = sum[c] * invM;
    float var = sumsq[c] * invM - m * m;
    float sc  = g[c] * rsqrtf(var + 1e-5f);
    g_scale[c] = sc;
    g_shift[c] = be[c] - m * sc;
}

__global__ void bnapply_kernel(float* __restrict__ X, int mask, int relu) {
    size_t i = (size_t)blockIdx.x * 256 + threadIdx.x;
    int c = (int)i & mask;
    float v = X[i] * g_scale[c] + g_shift[c];
    if (relu) v = fmaxf(v, 0.f);
    X[i] = v;
}

// ---------------- fused logits + dual argmax (R0 verbatim) ----------------
__global__ __launch_bounds__(256) void logits_argmax_kernel(
    const float* __restrict__ Z, const float* __restrict__ cb,
    const float* __restrict__ u, const float* __restrict__ lt,
    float* __restrict__ idx_out, int* __restrict__ code_out)
{
    extern __shared__ float sm[];
    float* zs = sm;                 // [32][64]
    float* gs = sm + 32 * 64;       // [64][256]
    float* ls = gs + 64 * 256;      // [64][256]
    __shared__ float swv[8], swnv[8];
    __shared__ int   swi[8], swni[8];

    const int tid = threadIdx.x;
    const int q   = blockIdx.y;
    const int r0  = blockIdx.x * 64;
    const float scale = expf(-lt[q]);

    for (int i = tid; i < 64 * 256; i += 256) {
        int r = i >> 8;
        float uu = u[((size_t)(r0 + r) * QQ + q) * CC + tid];
        uu = fminf(fmaxf(uu, 1e-9f), 1.0f);
        gs[i] = -logf(-logf(uu) + 1e-20f);
    }

    float acc[64];
#pragma unroll
    for (int r = 0; r < 64; r++) acc[r] = 0.f;

    const float* cbrow = cb + ((size_t)q * CC + tid) * DD;

    for (int kc = 0; kc < 256; kc += 32) {
        __syncthreads();
#pragma unroll
        for (int i = 0; i < 2; i++) {
            int idx = tid + i * 256;
            int r  = idx >> 3;
            int k4 = (idx & 7) << 2;
            float4 v = *(const float4*)(Z + (size_t)(r0 + r) * (QQ * DD) + q * DD + kc + k4);
            zs[(k4 + 0) * 64 + r] = v.x; zs[(k4 + 1) * 64 + r] = v.y;
            zs[(k4 + 2) * 64 + r] = v.z; zs[(k4 + 3) * 64 + r] = v.w;
        }
        __syncthreads();
#pragma unroll
        for (int k4 = 0; k4 < 8; k4++) {
            float4 w4 = *(const float4*)(cbrow + kc + k4 * 4);
            float wv[4] = {w4.x, w4.y, w4.z, w4.w};
#pragma unroll
            for (int kk = 0; kk < 4; kk++) {
                const float* zrow = zs + (k4 * 4 + kk) * 64;
                float w = wv[kk];
#pragma unroll
                for (int r4 = 0; r4 < 16; r4++) {
                    float4 z4 = *(const float4*)(zrow + r4 * 4);
                    acc[r4 * 4 + 0] += z4.x * w;
                    acc[r4 * 4 + 1] += z4.y * w;
                    acc[r4 * 4 + 2] += z4.z * w;
                    acc[r4 * 4 + 3] += z4.w * w;
                }
            }
        }
    }
#pragma unroll
    for (int r = 0; r < 64; r++) ls[r * 256 + tid] = acc[r];
    __syncthreads();

    const int lane = tid & 31, wid = tid >> 5;
    for (int r = 0; r < 64; r++) {
        float rv = ls[r * 256 + tid]; int ri = tid;
        float nv = rv * scale + gs[r * 256 + tid]; int ni = tid;
#pragma unroll
        for (int off = 16; off; off >>= 1) {
            float orv = __shfl_down_sync(0xffffffffu, rv, off);
            int   ori = __shfl_down_sync(0xffffffffu, ri, off);
            float onv = __shfl_down_sync(0xffffffffu, nv, off);
            int   oni = __shfl_down_sync(0xffffffffu, ni, off);
            if (orv > rv || (orv == rv && ori < ri)) { rv = orv; ri = ori; }
            if (onv > nv || (onv == nv && oni < ni)) { nv = onv; ni = oni; }
        }
        if (lane == 0) { swv[wid] = rv; swi[wid] = ri; swnv[wid] = nv; swni[wid] = ni; }
        __syncthreads();
        if (tid == 0) {
            float brv = swv[0];  int bri = swi[0];
            float bnv = swnv[0]; int bni = swni[0];
#pragma unroll
            for (int w = 1; w < 8; w++) {
                if (swv[w]  > brv || (swv[w]  == brv && swi[w]  < bri)) { brv = swv[w];  bri = swi[w]; }
                if (swnv[w] > bnv || (swnv[w] == bnv && swni[w] < bni)) { bnv = swnv[w]; bni = swni[w]; }
            }
            size_t o = (size_t)(r0 + r) * QQ + q;
            idx_out[o]  = (float)bri;
            code_out[o] = bni;
        }
        __syncthreads();
    }
}

// ---------------- embedding gather (R0 verbatim) ----------------
__global__ void embed_kernel(const int* __restrict__ code, const float* __restrict__ cb,
                             float* __restrict__ emb) {
    int bt = blockIdx.x;
    int d  = threadIdx.x;
    float s = 0.f;
#pragma unroll
    for (int q = 0; q < QQ; q++) {
        int ci = code[bt * QQ + q];
        s += cb[((size_t)(q * CC + ci)) * DD + d];
    }
    emb[(size_t)bt * DD + d] = s;
}

__global__ void finalize_loss_kernel(float* __restrict__ out) {
    out[0] = g_loss[0] * (1.0f / (float)XR_N);
}

// ======================================================================
// ===== tf32x3 tensor-core GEMM (decoder values path only) ============
// ======================================================================
__device__ __forceinline__ float tf32_rna(float v) {
    uint32_t r; asm("cvt.rna.tf32.f32 %0, %1;" : "=r"(r) : "f"(v));
    return __uint_as_float(r);
}
__device__ __forceinline__ void split4(const float4& v, float4& h, float4& l) {
    h.x = tf32_rna(v.x); l.x = tf32_rna(v.x - h.x);
    h.y = tf32_rna(v.y); l.y = tf32_rna(v.y - h.y);
    h.z = tf32_rna(v.z); l.z = tf32_rna(v.z - h.z);
    h.w = tf32_rna(v.w); l.w = tf32_rna(v.w - h.w);
}
__device__ __forceinline__ void mma8(float* d, const uint32_t* a, const uint32_t* b) {
    asm volatile(
        "mma.sync.aligned.m16n8k8.row.col.f32.tf32.tf32.f32 "
        "{%0,%1,%2,%3}, {%4,%5,%6,%7}, {%8,%9}, {%0,%1,%2,%3};"
        : "+f"(d[0]), "+f"(d[1]), "+f"(d[2]), "+f"(d[3])
        : "r"(a[0]), "r"(a[1]), "r"(a[2]), "r"(a[3]), "r"(b[0]), "r"(b[1]));
}

#define KC    32
#define PITCH 36
#define STG_F (128*PITCH)
#define GSMEM (4*2*STG_F*4)

__global__ __launch_bounds__(256, 1)
void gemm_mma(const float* __restrict__ A, int lda,
              const float* __restrict__ W, int ldw,
              const float* __restrict__ bias,
              float* __restrict__ C, int ldc,
              int K,
              const float* __restrict__ ref, float* __restrict__ lossAcc)
{
    extern __shared__ float smd[];
    __shared__ float s_red[8];

    const int tid  = threadIdx.x;
    const int lane = tid & 31;
    const int wid  = tid >> 5;
    const int wm   = wid >> 2;
    const int wn   = wid & 3;
    const int m0   = blockIdx.y * 128;
    const int n0   = blockIdx.x * 128;

    auto aH = [&](int s) { return smd + (size_t)s * (2 * STG_F); };
    auto aL = [&](int s) { return aH(s) + STG_F; };
    auto wH = [&](int s) { return smd + 4 * STG_F + (size_t)s * (2 * STG_F); };
    auto wL = [&](int s) { return wH(s) + STG_F; };

    const int row = tid >> 1;
    const int kb  = (tid & 1) * 16;

    float acc[4][4][4];
#pragma unroll
    for (int i = 0; i < 4; i++)
#pragma unroll
        for (int j = 0; j < 4; j++)
#pragma unroll
            for (int r = 0; r < 4; r++) acc[i][j][r] = 0.f;

    const int nk = K / KC;

    {
#pragma unroll
        for (int j = 0; j < 4; j++) {
            int k = kb + j * 4;
            float4 v = __ldg((const float4*)(A + (size_t)(m0 + row) * lda + k));
            float4 h, l; split4(v, h, l);
            *(float4*)(aH(0) + row * PITCH + k) = h;
            *(float4*)(aL(0) + row * PITCH + k) = l;
            float4 wv = __ldg((const float4*)(W + (size_t)(n0 + row) * ldw + k));
            split4(wv, h, l);
            *(float4*)(wH(0) + row * PITCH + k) = h;
            *(float4*)(wL(0) + row * PITCH + k) = l;
        }
    }
    __syncthreads();

    for (int c = 0; c < nk; c++) {
        const int s = c & 1;

        float4 vA[4], vW[4];
        const bool more = (c + 1 < nk);
        if (more) {
            int k0n = (c + 1) * KC;
#pragma unroll
            for (int j = 0; j < 4; j++) {
                int k = k0n + kb + j * 4;
                vA[j] = __ldg((const float4*)(A + (size_t)(m0 + row) * lda + k));
                vW[j] = __ldg((const float4*)(W + (size_t)(n0 + row) * ldw + k));
            }
        }

        const float* pAH = aH(s);
        const float* pAL = aL(s);
        const float* pWH = wH(s);
        const float* pWL = wL(s);
#pragma unroll
        for (int ks = 0; ks < 4; ks++) {
            const int kc = ks * 8 + (lane & 3);
            uint32_t ahi[4][4], alo[4][4], bhi[4][2], blo[4][2];
#pragma unroll
            for (int mi = 0; mi < 4; mi++) {
                int rb = (wm * 64 + mi * 16 + (lane >> 2)) * PITCH + kc;
                ahi[mi][0] = __float_as_uint(pAH[rb]);
                ahi[mi][1] = __float_as_uint(pAH[rb + 8 * PITCH]);
                ahi[mi][2] = __float_as_uint(pAH[rb + 4]);
                ahi[mi][3] = __float_as_uint(pAH[rb + 8 * PITCH + 4]);
                alo[mi][0] = __float_as_uint(pAL[rb]);
                alo[mi][1] = __float_as_uint(pAL[rb + 8 * PITCH]);
                alo[mi][2] = __float_as_uint(pAL[rb + 4]);
                alo[mi][3] = __float_as_uint(pAL[rb + 8 * PITCH + 4]);
            }
#pragma unroll
            for (int ni = 0; ni < 4; ni++) {
                int nb = (wn * 32 + ni * 8 + (lane >> 2)) * PITCH + kc;
                bhi[ni][0] = __float_as_uint(pWH[nb]);
                bhi[ni][1] = __float_as_uint(pWH[nb + 4]);
                blo[ni][0] = __float_as_uint(pWL[nb]);
                blo[ni][1] = __float_as_uint(pWL[nb + 4]);
            }
#pragma unroll
            for (int mi = 0; mi < 4; mi++)
#pragma unroll
                for (int ni = 0; ni < 4; ni++) {
                    mma8(acc[mi][ni], ahi[mi], bhi[ni]);
                    mma8(acc[mi][ni], ahi[mi], blo[ni]);
                    mma8(acc[mi][ni], alo[mi], bhi[ni]);
                }
        }

        if (more) {
            __syncthreads();
            const int so = s ^ 1;
#pragma unroll
            for (int j = 0; j < 4; j++) {
                int k = kb + j * 4;
                float4 h, l;
                split4(vA[j], h, l);
                *(float4*)(aH(so) + row * PITCH + k) = h;
                *(float4*)(aL(so) + row * PITCH + k) = l;
                split4(vW[j], h, l);
                *(float4*)(wH(so) + row * PITCH + k) = h;
                *(float4*)(wL(so) + row * PITCH + k) = l;
            }
            __syncthreads();
        }
    }

    float lsum = 0.f;
#pragma unroll
    for (int mi = 0; mi < 4; mi++) {
#pragma unroll
        for (int h = 0; h < 2; h++) {
            const size_t m = (size_t)(m0 + wm * 64 + mi * 16 + (lane >> 2) + h * 8);
#pragma unroll
            for (int ni = 0; ni < 4; ni++) {
                const int col = n0 + wn * 32 + ni * 8 + 2 * (lane & 3);
                float v0 = acc[mi][ni][2 * h + 0];
                float v1 = acc[mi][ni][2 * h + 1];
                if (bias) { v0 += __ldg(bias + col); v1 += __ldg(bias + col + 1); }
                if (ref) {
                    float d0 = v0 - __ldg(ref + m * ldc + col);
                    float d1 = v1 - __ldg(ref + m * ldc + col + 1);
                    lsum += d0 * d0 + d1 * d1;
                }
                *(float2*)(C + m * ldc + col) = make_float2(v0, v1);
            }
        }
    }
    if (lossAcc) {
#pragma unroll
        for (int off = 16; off; off >>= 1)
            lsum += __shfl_down_sync(0xffffffffu, lsum, off);
        if (lane == 0) s_red[wid] = lsum;
        __syncthreads();
        if (tid == 0) {
            float s = 0.f;
#pragma unroll
            for (int w = 0; w < 8; w++) s += s_red[w];
            atomicAdd(lossAcc, s);
        }
    }
}

// ---------------- host orchestration ----------------
extern "C" void kernel_launch(void* const* d_in, const int* in_sizes, int n_in,
                              void* d_out, int out_size) {
    const float* x       = (const float*)d_in[0];
    const float* u       = (const float*)d_in[1];
    const float* cb      = (const float*)d_in[2];
    const float* lt      = (const float*)d_in[3];
    const float* enc_w0  = (const float*)d_in[4];
    const float* enc_b0  = (const float*)d_in[5];
    const float* enc_g0  = (const float*)d_in[6];
    const float* enc_be0 = (const float*)d_in[7];
    const float* enc_w1  = (const float*)d_in[8];
    const float* enc_b1  = (const float*)d_in[9];
    const float* enc_g1  = (const float*)d_in[10];
    const float* enc_be1 = (const float*)d_in[11];
    const float* enc_wo  = (const float*)d_in[12];
    const float* enc_bo  = (const float*)d_in[13];
    const float* dec_g   = (const float*)d_in[14];
    const float* dec_be  = (const float*)d_in[15];
    const float* dec_w0  = (const float*)d_in[16];
    const float* dec_b0  = (const float*)d_in[17];
    const float* dec_g0  = (const float*)d_in[18];
    const float* dec_be0 = (const float*)d_in[19];
    const float* dec_w1  = (const float*)d_in[20];
    const float* dec_b1  = (const float*)d_in[21];
    const float* dec_g1  = (const float*)d_in[22];
    const float* dec_be1 = (const float*)d_in[23];
    const float* fin_w   = (const float*)d_in[24];
    const float* fin_b   = (const float*)d_in[25];
    float* out = (float*)d_out;

    float *xt, *h0, *h1, *z, *emb, *sum, *sumsq, *loss;
    int* code;
    cudaGetSymbolAddress((void**)&xt,   g_xt);
    cudaGetSymbolAddress((void**)&h0,   g_h0);
    cudaGetSymbolAddress((void**)&h1,   g_h1);
    cudaGetSymbolAddress((void**)&z,    g_z);
    cudaGetSymbolAddress((void**)&emb,  g_emb);
    cudaGetSymbolAddress((void**)&code, g_code);
    cudaGetSymbolAddress((void**)&sum,  g_sum);
    cudaGetSymbolAddress((void**)&sumsq,g_sumsq);
    cudaGetSymbolAddress((void**)&loss, g_loss);

    cudaFuncSetAttribute(logits_argmax_kernel,
                         cudaFuncAttributeMaxDynamicSharedMemorySize, 139264);
    cudaFuncSetAttribute(gemm_mma, cudaFuncAttributeMaxDynamicSharedMemorySize, GSMEM);

    auto run_bn = [&](float* X, int N, const float* g, const float* be, int relu) {
        cudaMemsetAsync(sum,   0, N * sizeof(float));
        cudaMemsetAsync(sumsq, 0, N * sizeof(float));
        colstats_kernel<<<dim3(N / 32, 8), dim3(32, 8)>>>(X, N, sum, sumsq);
        bnparams_kernel<<<(N + 127) / 128, 128>>>(sum, sumsq, g, be, N);
        bnapply_kernel<<<(unsigned)(((size_t)MROWS * N) / 256), 256>>>(X, N - 1, relu);
    };

    // ===== encoder: R0-exact (fp32 SIMT) — decisions depend on this =====
    transpose_kernel<<<dim3(TT / 32, DIMV / 32, BB), dim3(32, 8)>>>(x, xt);
    gemm128<<<dim3(HIDV / 128, MROWS / 128), 256>>>(xt, enc_w0, enc_b0, h0,
                                                    MROWS, HIDV, DIMV, nullptr, nullptr);
    run_bn(h0, HIDV, enc_g0, enc_be0, 1);
    gemm128<<<dim3(HIDV / 128, MROWS / 128), 256>>>(h0, enc_w1, enc_b1, h1,
                                                    MROWS, HIDV, HIDV, nullptr, nullptr);
    run_bn(h1, HIDV, enc_g1, enc_be1, 1);
    gemm128<<<dim3((QQ * DD) / 128, MROWS / 128), 256>>>(h1, enc_wo, enc_bo, z,
                                                         MROWS, QQ * DD, HIDV, nullptr, nullptr);

    // ===== quantization: R0-exact fused logits + dual argmax =====
    logits_argmax_kernel<<<dim3(MROWS / 64, QQ), 256, 139264>>>(z, cb, u, lt,
                                                                out + XR_N, code);
    embed_kernel<<<MROWS, DD>>>(code, cb, emb);

    // ===== decoder: values-only path, tf32x3 tensor cores =====
    run_bn(emb, DD, dec_g, dec_be, 0);
    gemm_mma<<<dim3(HIDV / 128, MROWS / 128), 256, GSMEM>>>(
        emb, DD, dec_w0, DD, dec_b0, h0, HIDV, DD, nullptr, nullptr);
    run_bn(h0, HIDV, dec_g0, dec_be0, 1);
    gemm_mma<<<dim3(HIDV / 128, MROWS / 128), 256, GSMEM>>>(
        h0, HIDV, dec_w1, HIDV, dec_b1, h1, HIDV, HIDV, nullptr, nullptr);
    run_bn(h1, HIDV, dec_g1, dec_be1, 1);

    // final linear + fused MSE loss vs xt
    cudaMemsetAsync(loss, 0, sizeof(float));
    gemm_mma<<<dim3(DIMV / 128, MROWS / 128), 256, GSMEM>>>(
        h1, HIDV, fin_w, HIDV, fin_b, out, DIMV, HIDV, xt, loss);
    finalize_loss_kernel<<<1, 1>>>(out + XR_N + IDX_N);
}

// round 6
// speedup vs baseline: 1.9818x; 1.8732x over previous
#include <cuda_runtime.h>
#include <cuda_fp16.h>
#include <math.h>
#include <stdint.h>

// Problem constants
#define BB    32
#define TT    512
#define DIMV  512
#define QQ    8
#define CC    256
#define DD    256
#define HIDV  1024
#define MROWS (BB*TT)          // 16384
#define XR_N  (MROWS*DIMV)     // 8388608
#define IDX_N (MROWS*QQ)       // 131072

// ---------------- scratch ----------------
__device__ float g_xt [MROWS*DIMV];
__device__ float g_h0 [MROWS*HIDV];
__device__ float g_h1 [MROWS*HIDV];
__device__ float g_z  [MROWS*QQ*DD];
__device__ float g_logits[(size_t)QQ*MROWS*CC];
__device__ float g_emb[MROWS*DD];
__device__ int   g_code[MROWS*QQ];
__device__ float g_sum[2048];
__device__ float g_sumsq[2048];
__device__ float g_scale[2048];
__device__ float g_shift[2048];
__device__ float g_loss[1];

// ======================= fp16x3 helpers =======================
#define INV2048 4.8828125e-4f

__device__ __forceinline__ void split2h(float a, float b, uint32_t& hi, uint32_t& lo) {
    __half ha = __float2half_rn(a), hb = __float2half_rn(b);
    float ra = (a - __half2float(ha)) * 2048.0f;
    float rb = (b - __half2float(hb)) * 2048.0f;
    __half2 h = __halves2half2(ha, hb);
    __half2 l = __halves2half2(__float2half_rn(ra), __float2half_rn(rb));
    hi = *(uint32_t*)&h;
    lo = *(uint32_t*)&l;
}

__device__ __forceinline__ void mma16(float* d, const uint32_t* a, const uint32_t* b) {
    asm volatile(
        "mma.sync.aligned.m16n8k16.row.col.f32.f16.f16.f32 "
        "{%0,%1,%2,%3}, {%4,%5,%6,%7}, {%8,%9}, {%0,%1,%2,%3};"
        : "+f"(d[0]), "+f"(d[1]), "+f"(d[2]), "+f"(d[3])
        : "r"(a[0]), "r"(a[1]), "r"(a[2]), "r"(a[3]), "r"(b[0]), "r"(b[1]));
}

// ======================= fp16x3 GEMM via mma.sync.m16n8k16 =======================
// C[M,N] = A[M,K] @ W[N,K]^T (+bias), fp32 in/out, fp16x3 split (fp32-grade).
// CTA 128x128, 8 warps (warp tile 64x32), KC=32, double-buffered smem half2
// tiles with pitch 20 (conflict-free fragment loads). Dual accumulators:
// acc = hi*hi, acc2 = hi*lo + lo*hi (lo prescaled by 2048; combined at end).
// Optional per-q block offsets (gridDim.z) and fused MSE loss vs ref.
#define KC    32
#define P2    20                 // half2 pitch per row
#define SP    (128*P2)           // half2 per matrix-half per stage (2560)
#define GSMEM2 (8*SP*4)          // 8 half-stage buffers * 4B = 81920

__global__ __launch_bounds__(256, 1)
void gemm_f16x3(const float* __restrict__ A, int lda, long long aQ,
                const float* __restrict__ W, int ldw, long long wQ,
                const float* __restrict__ bias,
                float* __restrict__ C, int ldc, long long cQ,
                int K,
                const float* __restrict__ ref, float* __restrict__ lossAcc)
{
    extern __shared__ uint32_t smu[];
    __shared__ float s_red[8];

    const int tid  = threadIdx.x;
    const int lane = tid & 31;
    const int wid  = tid >> 5;
    const int wm   = wid >> 2;        // 0..1
    const int wn   = wid & 3;         // 0..3
    const int m0   = blockIdx.y * 128;
    const int n0   = blockIdx.x * 128;
    const int q    = blockIdx.z;
    A += (size_t)q * aQ;
    W += (size_t)q * wQ;
    C += (size_t)q * cQ;

    uint32_t* AH = smu;               // [2][SP]
    uint32_t* AL = smu + 2 * SP;
    uint32_t* WH = smu + 4 * SP;
    uint32_t* WL = smu + 6 * SP;

    const int row = tid >> 1;         // staging row 0..127
    const int kb  = (tid & 1) * 16;   // staging k-half (floats)

    float acc [4][4][4];
    float acc2[4][4][4];
#pragma unroll
    for (int i = 0; i < 4; i++)
#pragma unroll
        for (int j = 0; j < 4; j++)
#pragma unroll
            for (int r = 0; r < 4; r++) { acc[i][j][r] = 0.f; acc2[i][j][r] = 0.f; }

    const int nk = K / KC;

    // ---- stage chunk 0 into stage 0 ----
#pragma unroll
    for (int j = 0; j < 4; j++) {
        int k = kb + j * 4;
        float4 va = __ldg((const float4*)(A + (size_t)(m0 + row) * lda + k));
        uint32_t h0, h1, l0, l1;
        split2h(va.x, va.y, h0, l0);
        split2h(va.z, va.w, h1, l1);
        int o = row * P2 + (k >> 1);
        *(uint2*)&AH[o] = make_uint2(h0, h1);
        *(uint2*)&AL[o] = make_uint2(l0, l1);
        float4 vw = __ldg((const float4*)(W + (size_t)(n0 + row) * ldw + k));
        split2h(vw.x, vw.y, h0, l0);
        split2h(vw.z, vw.w, h1, l1);
        *(uint2*)&WH[o] = make_uint2(h0, h1);
        *(uint2*)&WL[o] = make_uint2(l0, l1);
    }
    __syncthreads();

    for (int c = 0; c < nk; c++) {
        const int s  = c & 1;
        const int sS = s * SP;

        // prefetch chunk c+1 into registers
        float4 vA[4], vW[4];
        const bool more = (c + 1 < nk);
        if (more) {
            int k0n = (c + 1) * KC;
#pragma unroll
            for (int j = 0; j < 4; j++) {
                int k = k0n + kb + j * 4;
                vA[j] = __ldg((const float4*)(A + (size_t)(m0 + row) * lda + k));
                vW[j] = __ldg((const float4*)(W + (size_t)(n0 + row) * ldw + k));
            }
        }

        // mma over stage s: 2 k16 steps
#pragma unroll
        for (int ks = 0; ks < 2; ks++) {
            const int cc = ks * 8 + (lane & 3);
            uint32_t bh[4][2], bl[4][2];
#pragma unroll
            for (int ni = 0; ni < 4; ni++) {
                int br = (wn * 32 + ni * 8 + (lane >> 2)) * P2 + cc;
                bh[ni][0] = WH[sS + br];
                bh[ni][1] = WH[sS + br + 4];
                bl[ni][0] = WL[sS + br];
                bl[ni][1] = WL[sS + br + 4];
            }
#pragma unroll
            for (int mi = 0; mi < 4; mi++) {
                int ar0 = (wm * 64 + mi * 16 + (lane >> 2)) * P2 + cc;
                int ar1 = ar0 + 8 * P2;
                uint32_t ah[4], al[4];
                ah[0] = AH[sS + ar0]; ah[1] = AH[sS + ar1];
                ah[2] = AH[sS + ar0 + 4]; ah[3] = AH[sS + ar1 + 4];
                al[0] = AL[sS + ar0]; al[1] = AL[sS + ar1];
                al[2] = AL[sS + ar0 + 4]; al[3] = AL[sS + ar1 + 4];
#pragma unroll
                for (int ni = 0; ni < 4; ni++) {
                    mma16(acc [mi][ni], ah, bh[ni]);
                    mma16(acc2[mi][ni], ah, bl[ni]);
                    mma16(acc2[mi][ni], al, bh[ni]);
                }
            }
        }

        if (more) {
            __syncthreads();
            const int so = (s ^ 1) * SP;
#pragma unroll
            for (int j = 0; j < 4; j++) {
                int k = kb + j * 4;
                uint32_t h0, h1, l0, l1;
                split2h(vA[j].x, vA[j].y, h0, l0);
                split2h(vA[j].z, vA[j].w, h1, l1);
                int o = row * P2 + (k >> 1);
                *(uint2*)&AH[so + o] = make_uint2(h0, h1);
                *(uint2*)&AL[so + o] = make_uint2(l0, l1);
                split2h(vW[j].x, vW[j].y, h0, l0);
                split2h(vW[j].z, vW[j].w, h1, l1);
                *(uint2*)&WH[so + o] = make_uint2(h0, h1);
                *(uint2*)&WL[so + o] = make_uint2(l0, l1);
            }
            __syncthreads();
        }
    }

    // epilogue: v = acc + acc2/2048 (+bias); optional fused MSE vs ref
    float lsum = 0.f;
#pragma unroll
    for (int mi = 0; mi < 4; mi++) {
#pragma unroll
        for (int h = 0; h < 2; h++) {
            const size_t m = (size_t)(m0 + wm * 64 + mi * 16 + (lane >> 2) + h * 8);
#pragma unroll
            for (int ni = 0; ni < 4; ni++) {
                const int col = n0 + wn * 32 + ni * 8 + 2 * (lane & 3);
                float v0 = acc[mi][ni][2 * h + 0] + acc2[mi][ni][2 * h + 0] * INV2048;
                float v1 = acc[mi][ni][2 * h + 1] + acc2[mi][ni][2 * h + 1] * INV2048;
                if (bias) { v0 += __ldg(bias + col); v1 += __ldg(bias + col + 1); }
                if (ref) {
                    float d0 = v0 - __ldg(ref + m * ldc + col);
                    float d1 = v1 - __ldg(ref + m * ldc + col + 1);
                    lsum += d0 * d0 + d1 * d1;
                }
                *(float2*)(C + m * ldc + col) = make_float2(v0, v1);
            }
        }
    }
    if (lossAcc) {
#pragma unroll
        for (int off = 16; off; off >>= 1)
            lsum += __shfl_down_sync(0xffffffffu, lsum, off);
        if (lane == 0) s_red[wid] = lsum;
        __syncthreads();
        if (tid == 0) {
            float s = 0.f;
#pragma unroll
            for (int w = 0; w < 8; w++) s += s_red[w];
            atomicAdd(lossAcc, s);
        }
    }
}

// ---------------- transpose ----------------
__global__ void transpose_kernel(const float* __restrict__ x, float* __restrict__ xt) {
    __shared__ float tile[32][33];
    int b  = blockIdx.z;
    int t0 = blockIdx.x * 32;
    int d0 = blockIdx.y * 32;
    int tx = threadIdx.x, ty = threadIdx.y;
    const float* xb = x  + (size_t)b * DIMV * TT;
    float*      xtb = xt + (size_t)b * TT * DIMV;
#pragma unroll
    for (int j = 0; j < 32; j += 8)
        tile[ty + j][tx] = xb[(size_t)(d0 + ty + j) * TT + t0 + tx];
    __syncthreads();
#pragma unroll
    for (int j = 0; j < 32; j += 8)
        xtb[(size_t)(t0 + ty + j) * DIMV + d0 + tx] = tile[tx][ty + j];
}

// ---------------- BN kernels ----------------
__global__ void colstats_kernel(const float* __restrict__ X, int N,
                                float* __restrict__ sum, float* __restrict__ sumsq) {
    int col = blockIdx.x * 32 + threadIdx.x;
    int r0  = blockIdx.y * 2048;
    float s = 0.f, ss = 0.f;
    for (int r = r0 + threadIdx.y; r < r0 + 2048; r += 8) {
        float v = X[(size_t)r * N + col];
        s += v; ss += v * v;
    }
    __shared__ float sh [8][32];
    __shared__ float sh2[8][32];
    sh [threadIdx.y][threadIdx.x] = s;
    sh2[threadIdx.y][threadIdx.x] = ss;
    __syncthreads();
    if (threadIdx.y == 0) {
#pragma unroll
        for (int w = 1; w < 8; w++) { s += sh[w][threadIdx.x]; ss += sh2[w][threadIdx.x]; }
        atomicAdd(&sum[col], s);
        atomicAdd(&sumsq[col], ss);
    }
}

__global__ void bnparams_kernel(const float* __restrict__ sum, const float* __restrict__ sumsq,
                                const float* __restrict__ g, const float* __restrict__ be, int N) {
    int c = blockIdx.x * 128 + threadIdx.x;
    if (c >= N) return;
    const float invM = 1.0f / (float)MROWS;
    float m   = sum[c] * invM;
    float var = sumsq[c] * invM - m * m;
    float sc  = g[c] * rsqrtf(var + 1e-5f);
    g_scale[c] = sc;
    g_shift[c] = be[c] - m * sc;
}

__global__ void bnapply_kernel(float* __restrict__ X, int mask, int relu) {
    size_t i = (size_t)blockIdx.x * 256 + threadIdx.x;
    int c = (int)i & mask;
    float v = X[i] * g_scale[c] + g_shift[c];
    if (relu) v = fmaxf(v, 0.f);
    X[i] = v;
}

// ---------------- gumbel ----------------
__device__ __forceinline__ float gumbel_of(float uu) {
    uu = fminf(fmaxf(uu, 1e-9f), 1.0f);
    return -logf(-logf(uu) + 1e-20f);
}

// ---------------- dual argmax with exact fp32 refinement ----------------
__global__ __launch_bounds__(256) void argmax_kernel(
    const float* __restrict__ logits, const float* __restrict__ z,
    const float* __restrict__ cb, const float* __restrict__ u,
    const float* __restrict__ lt, float* __restrict__ idx_out, int* __restrict__ code_out)
{
    const int q    = blockIdx.y;
    const int row  = blockIdx.x * 8 + (threadIdx.x >> 5);
    const int lane = threadIdx.x & 31;
    const float scale = expf(-__ldg(lt + q));
    const float* lrow = logits + ((size_t)q * MROWS + row) * CC;
    const float* urow = u + ((size_t)row * QQ + q) * CC;

    float lv[8], nn[8];
    bool exR[8], exN[8];
#pragma unroll
    for (int it = 0; it < 8; it++) {
        int c = it * 32 + lane;
        lv[it] = __ldg(lrow + c);
        nn[it] = lv[it] * scale + gumbel_of(__ldg(urow + c));
        exR[it] = false; exN[it] = false;
    }

    int candR[3], candN[3];
#pragma unroll
    for (int r = 0; r < 3; r++) {
        float bv = -INFINITY; int bi = 1 << 30;
#pragma unroll
        for (int it = 0; it < 8; it++)
            if (!exR[it] && (lv[it] > bv || (lv[it] == bv && it * 32 + lane < bi))) {
                bv = lv[it]; bi = it * 32 + lane;
            }
#pragma unroll
        for (int off = 16; off; off >>= 1) {
            float ov = __shfl_down_sync(0xffffffffu, bv, off);
            int   oi = __shfl_down_sync(0xffffffffu, bi, off);
            if (ov > bv || (ov == bv && oi < bi)) { bv = ov; bi = oi; }
        }
        bi = __shfl_sync(0xffffffffu, bi, 0);
        candR[r] = bi;
        if ((bi & 31) == lane) exR[bi >> 5] = true;

        bv = -INFINITY; bi = 1 << 30;
#pragma unroll
        for (int it = 0; it < 8; it++)
            if (!exN[it] && (nn[it] > bv || (nn[it] == bv && it * 32 + lane < bi))) {
                bv = nn[it]; bi = it * 32 + lane;
            }
#pragma unroll
        for (int off = 16; off; off >>= 1) {
            float ov = __shfl_down_sync(0xffffffffu, bv, off);
            int   oi = __shfl_down_sync(0xffffffffu, bi, off);
            if (ov > bv || (ov == bv && oi < bi)) { bv = ov; bi = oi; }
        }
        bi = __shfl_sync(0xffffffffu, bi, 0);
        candN[r] = bi;
        if ((bi & 31) == lane) exN[bi >> 5] = true;
    }

    const float* zrow = z + (size_t)row * (QQ * DD) + q * DD;
    float4 z0 = __ldg((const float4*)(zrow + lane * 8));
    float4 z1 = __ldg((const float4*)(zrow + lane * 8 + 4));
    float dR[3], dN[3];
#pragma unroll
    for (int r = 0; r < 3; r++) {
#pragma unroll
        for (int pass = 0; pass < 2; pass++) {
            int c = pass ? candN[r] : candR[r];
            const float* crow = cb + ((size_t)q * CC + c) * DD;
            float4 c0 = __ldg((const float4*)(crow + lane * 8));
            float4 c1 = __ldg((const float4*)(crow + lane * 8 + 4));
            float d = z0.x * c0.x + z0.y * c0.y + z0.z * c0.z + z0.w * c0.w
                    + z1.x * c1.x + z1.y * c1.y + z1.z * c1.z + z1.w * c1.w;
#pragma unroll
            for (int off = 16; off; off >>= 1)
                d += __shfl_down_sync(0xffffffffu, d, off);
            if (pass) dN[r] = d; else dR[r] = d;
        }
    }

    if (lane == 0) {
        int ri = candR[0]; float rv = dR[0];
#pragma unroll
        for (int r = 1; r < 3; r++)
            if (dR[r] > rv || (dR[r] == rv && candR[r] < ri)) { rv = dR[r]; ri = candR[r]; }
        int ni = candN[0];
        float nv = dN[0] * scale + gumbel_of(__ldg(urow + candN[0]));
#pragma unroll
        for (int r = 1; r < 3; r++) {
            float s = dN[r] * scale + gumbel_of(__ldg(urow + candN[r]));
            if (s > nv || (s == nv && candN[r] < ni)) { nv = s; ni = candN[r]; }
        }
        size_t o = (size_t)row * QQ + q;
        idx_out[o]  = (float)ri;
        code_out[o] = ni;
    }
}

// ---------------- embedding gather ----------------
__global__ void embed_kernel(const int* __restrict__ code, const float* __restrict__ cb,
                             float* __restrict__ emb) {
    int bt = blockIdx.x;
    int d  = threadIdx.x;
    float s = 0.f;
#pragma unroll
    for (int q = 0; q < QQ; q++) {
        int ci = code[bt * QQ + q];
        s += cb[((size_t)(q * CC + ci)) * DD + d];
    }
    emb[(size_t)bt * DD + d] = s;
}

__global__ void finalize_loss_kernel(float* __restrict__ out) {
    out[0] = g_loss[0] * (1.0f / (float)XR_N);
}

// ---------------- host orchestration ----------------
extern "C" void kernel_launch(void* const* d_in, const int* in_sizes, int n_in,
                              void* d_out, int out_size) {
    const float* x       = (const float*)d_in[0];
    const float* u       = (const float*)d_in[1];
    const float* cb      = (const float*)d_in[2];
    const float* lt      = (const float*)d_in[3];
    const float* enc_w0  = (const float*)d_in[4];
    const float* enc_b0  = (const float*)d_in[5];
    const float* enc_g0  = (const float*)d_in[6];
    const float* enc_be0 = (const float*)d_in[7];
    const float* enc_w1  = (const float*)d_in[8];
    const float* enc_b1  = (const float*)d_in[9];
    const float* enc_g1  = (const float*)d_in[10];
    const float* enc_be1 = (const float*)d_in[11];
    const float* enc_wo  = (const float*)d_in[12];
    const float* enc_bo  = (const float*)d_in[13];
    const float* dec_g   = (const float*)d_in[14];
    const float* dec_be  = (const float*)d_in[15];
    const float* dec_w0  = (const float*)d_in[16];
    const float* dec_b0  = (const float*)d_in[17];
    const float* dec_g0  = (const float*)d_in[18];
    const float* dec_be0 = (const float*)d_in[19];
    const float* dec_w1  = (const float*)d_in[20];
    const float* dec_b1  = (const float*)d_in[21];
    const float* dec_g1  = (const float*)d_in[22];
    const float* dec_be1 = (const float*)d_in[23];
    const float* fin_w   = (const float*)d_in[24];
    const float* fin_b   = (const float*)d_in[25];
    float* out = (float*)d_out;

    float *xt, *h0, *h1, *z, *logits, *emb, *sum, *sumsq, *loss;
    int* code;
    cudaGetSymbolAddress((void**)&xt,    g_xt);
    cudaGetSymbolAddress((void**)&h0,    g_h0);
    cudaGetSymbolAddress((void**)&h1,    g_h1);
    cudaGetSymbolAddress((void**)&z,     g_z);
    cudaGetSymbolAddress((void**)&logits,g_logits);
    cudaGetSymbolAddress((void**)&emb,   g_emb);
    cudaGetSymbolAddress((void**)&code,  g_code);
    cudaGetSymbolAddress((void**)&sum,   g_sum);
    cudaGetSymbolAddress((void**)&sumsq, g_sumsq);
    cudaGetSymbolAddress((void**)&loss,  g_loss);

    cudaFuncSetAttribute(gemm_f16x3, cudaFuncAttributeMaxDynamicSharedMemorySize, GSMEM2);

    auto run_bn = [&](float* X, int N, const float* g, const float* be, int relu) {
        cudaMemsetAsync(sum,   0, N * sizeof(float));
        cudaMemsetAsync(sumsq, 0, N * sizeof(float));
        colstats_kernel<<<dim3(N / 32, 8), dim3(32, 8)>>>(X, N, sum, sumsq);
        bnparams_kernel<<<(N + 127) / 128, 128>>>(sum, sumsq, g, be, N);
        bnapply_kernel<<<(unsigned)(((size_t)MROWS * N) / 256), 256>>>(X, N - 1, relu);
    };

    auto gemm = [&](const float* A, int lda, const float* W, int ldw, const float* bias,
                    float* C, int ldc, int N, int K, const float* ref, float* lAcc) {
        gemm_f16x3<<<dim3(N / 128, MROWS / 128, 1), 256, GSMEM2>>>(
            A, lda, 0, W, ldw, 0, bias, C, ldc, 0, K, ref, lAcc);
    };

    // ===== encoder (fp16x3, fp32-grade precision) =====
    transpose_kernel<<<dim3(TT / 32, DIMV / 32, BB), dim3(32, 8)>>>(x, xt);
    gemm(xt, DIMV, enc_w0, DIMV, enc_b0, h0, HIDV, HIDV, DIMV, nullptr, nullptr);
    run_bn(h0, HIDV, enc_g0, enc_be0, 1);
    gemm(h0, HIDV, enc_w1, HIDV, enc_b1, h1, HIDV, HIDV, HIDV, nullptr, nullptr);
    run_bn(h1, HIDV, enc_g1, enc_be1, 1);
    gemm(h1, HIDV, enc_wo, HIDV, enc_bo, z, QQ * DD, QQ * DD, HIDV, nullptr, nullptr);

    // ===== logits GEMM (per-q block-diagonal) + exact-refined dual argmax =====
    gemm_f16x3<<<dim3(CC / 128, MROWS / 128, QQ), 256, GSMEM2>>>(
        z, QQ * DD, DD,
        cb, DD, (long long)CC * DD,
        nullptr,
        logits, CC, (long long)MROWS * CC,
        DD, nullptr, nullptr);
    argmax_kernel<<<dim3(MROWS / 8, QQ), 256>>>(logits, z, cb, u, lt, out + XR_N, code);
    embed_kernel<<<MROWS, DD>>>(code, cb, emb);

    // ===== decoder (fp16x3) =====
    run_bn(emb, DD, dec_g, dec_be, 0);
    gemm(emb, DD, dec_w0, DD, dec_b0, h0, HIDV, HIDV, DD, nullptr, nullptr);
    run_bn(h0, HIDV, dec_g0, dec_be0, 1);
    gemm(h0, HIDV, dec_w1, HIDV, dec_b1, h1, HIDV, HIDV, HIDV, nullptr, nullptr);
    run_bn(h1, HIDV, dec_g1, dec_be1, 1);

    // final linear + fused MSE loss vs xt
    cudaMemsetAsync(loss, 0, sizeof(float));
    gemm_f16x3<<<dim3(DIMV / 128, MROWS / 128, 1), 256, GSMEM2>>>(
        h1, HIDV, 0, fin_w, HIDV, 0, fin_b, out, DIMV, 0, HIDV, xt, loss);
    finalize_loss_kernel<<<1, 1>>>(out + XR_N + IDX_N);
}

// round 7
// speedup vs baseline: 2.0370x; 1.0279x over previous
#include <cuda_runtime.h>
#include <cuda_fp16.h>
#include <math.h>
#include <stdint.h>

// Problem constants
#define BB    32
#define TT    512
#define DIMV  512
#define QQ    8
#define CC    256
#define DD    256
#define HIDV  1024
#define MROWS (BB*TT)          // 16384
#define XR_N  (MROWS*DIMV)     // 8388608
#define IDX_N (MROWS*QQ)       // 131072

// ---------------- fp32 scratch ----------------
__device__ float g_xt [MROWS*DIMV];
__device__ float g_h0 [MROWS*HIDV];
__device__ float g_h1 [MROWS*HIDV];
__device__ float g_z  [MROWS*QQ*DD];
__device__ float g_logits[(size_t)QQ*MROWS*CC];
__device__ float g_emb[MROWS*DD];
__device__ int   g_code[MROWS*QQ];
__device__ float g_sum[2048];
__device__ float g_sumsq[2048];
__device__ float g_scale[2048];
__device__ float g_shift[2048];
__device__ float g_loss[1];

// ---------------- pre-split half2 buffers (u32 = 2 halves) ----------------
__device__ uint32_t g_xtH [MROWS*DIMV/2],  g_xtL [MROWS*DIMV/2];
__device__ uint32_t g_h0H [MROWS*HIDV/2],  g_h0L [MROWS*HIDV/2];
__device__ uint32_t g_h1H [MROWS*HIDV/2],  g_h1L [MROWS*HIDV/2];
__device__ uint32_t g_zH  [MROWS*QQ*DD/2], g_zL  [MROWS*QQ*DD/2];
__device__ uint32_t g_embH[MROWS*DD/2],    g_embL[MROWS*DD/2];
__device__ uint32_t g_wH  [3014656],       g_wL  [3014656];
// weight pool offsets (u32 units)
#define OFF_W0   0
#define OFF_W1   262144
#define OFF_WO   786432
#define OFF_CB   1835008
#define OFF_DW0  2097152
#define OFF_DW1  2228224
#define OFF_FW   2752512

// ======================= fp16x3 helpers =======================
#define INV2048 4.8828125e-4f

__device__ __forceinline__ void split2h(float a, float b, uint32_t& hi, uint32_t& lo) {
    __half ha = __float2half_rn(a), hb = __float2half_rn(b);
    float ra = (a - __half2float(ha)) * 2048.0f;
    float rb = (b - __half2float(hb)) * 2048.0f;
    __half2 h = __halves2half2(ha, hb);
    __half2 l = __halves2half2(__float2half_rn(ra), __float2half_rn(rb));
    hi = *(uint32_t*)&h;
    lo = *(uint32_t*)&l;
}

__device__ __forceinline__ void mma16(float* d, const uint32_t* a, const uint32_t* b) {
    asm volatile(
        "mma.sync.aligned.m16n8k16.row.col.f32.f16.f16.f32 "
        "{%0,%1,%2,%3}, {%4,%5,%6,%7}, {%8,%9}, {%0,%1,%2,%3};"
        : "+f"(d[0]), "+f"(d[1]), "+f"(d[2]), "+f"(d[3])
        : "r"(a[0]), "r"(a[1]), "r"(a[2]), "r"(a[3]), "r"(b[0]), "r"(b[1]));
}

// ---------------- generic fp32 -> hi/lo split (weights, xt) ----------------
__global__ void split_mat(const float* __restrict__ X,
                          uint32_t* __restrict__ H, uint32_t* __restrict__ L) {
    size_t i = (size_t)blockIdx.x * 256 + threadIdx.x;
    float2 v = *(const float2*)(X + 2 * i);
    uint32_t h, l;
    split2h(v.x, v.y, h, l);
    H[i] = h; L[i] = l;
}

// ======================= pre-split fp16x3 GEMM =======================
// C[M,N] = A[M,K] @ W[N,K]^T (+bias); A,W given as packed half2 hi/lo.
// CTA 128x128, 8 warps (warp tile 64x32), KC=32 halves-pairs... (32 floats),
// double-buffered smem, pitch P2=20 u32. Dual accumulators (hi*hi | cross).
// Optional: per-q offsets, fused column stats, split C out, fused MSE loss.
#define KC    32
#define P2    20
#define SP    (128*P2)
#define GSMEM2 (8*SP*4)          // 81920 bytes

__global__ __launch_bounds__(256, 1)
void gemm_h(const uint32_t* __restrict__ AH, const uint32_t* __restrict__ AL,
            int lda2, long long aQ2,
            const uint32_t* __restrict__ WH, const uint32_t* __restrict__ WL,
            int ldw2, long long wQ2,
            const float* __restrict__ bias,
            float* __restrict__ C, int ldc, long long cQ,
            uint32_t* __restrict__ CH, uint32_t* __restrict__ CL, int ldc2,
            int K,
            float* __restrict__ statSum, float* __restrict__ statSumsq,
            const float* __restrict__ ref, float* __restrict__ lossAcc)
{
    extern __shared__ uint32_t smu[];
    __shared__ float s_red[8];

    const int tid  = threadIdx.x;
    const int lane = tid & 31;
    const int wid  = tid >> 5;
    const int wm   = wid >> 2;
    const int wn   = wid & 3;
    const int m0   = blockIdx.y * 128;
    const int n0   = blockIdx.x * 128;
    const int q    = blockIdx.z;
    AH += (size_t)q * aQ2;  AL += (size_t)q * aQ2;
    WH += (size_t)q * wQ2;  WL += (size_t)q * wQ2;
    C  += (size_t)q * cQ;

    uint32_t* sAH = smu;               // [2][SP]
    uint32_t* sAL = smu + 2 * SP;
    uint32_t* sWH = smu + 4 * SP;
    uint32_t* sWL = smu + 6 * SP;

    const int row = tid >> 1;          // staging row 0..127
    const int kb8 = (tid & 1) * 8;     // staging u32-half (0 or 8)

    float acc [4][4][4];
    float acc2[4][4][4];
#pragma unroll
    for (int i = 0; i < 4; i++)
#pragma unroll
        for (int j = 0; j < 4; j++)
#pragma unroll
            for (int r = 0; r < 4; r++) { acc[i][j][r] = 0.f; acc2[i][j][r] = 0.f; }

    const int nk = K / KC;             // chunk = 16 u32 per row

    const uint32_t* gAH = AH + (size_t)(m0 + row) * lda2 + kb8;
    const uint32_t* gAL = AL + (size_t)(m0 + row) * lda2 + kb8;
    const uint32_t* gWH = WH + (size_t)(n0 + row) * ldw2 + kb8;
    const uint32_t* gWL = WL + (size_t)(n0 + row) * ldw2 + kb8;
    const int so0 = row * P2 + kb8;

    // prologue: stage chunk 0 into stage 0
    {
        uint4 a0 = __ldg((const uint4*)(gAH));
        uint4 a1 = __ldg((const uint4*)(gAH + 4));
        uint4 b0 = __ldg((const uint4*)(gAL));
        uint4 b1 = __ldg((const uint4*)(gAL + 4));
        uint4 c0 = __ldg((const uint4*)(gWH));
        uint4 c1 = __ldg((const uint4*)(gWH + 4));
        uint4 d0 = __ldg((const uint4*)(gWL));
        uint4 d1 = __ldg((const uint4*)(gWL + 4));
        *(uint4*)&sAH[so0] = a0; *(uint4*)&sAH[so0 + 4] = a1;
        *(uint4*)&sAL[so0] = b0; *(uint4*)&sAL[so0 + 4] = b1;
        *(uint4*)&sWH[so0] = c0; *(uint4*)&sWH[so0 + 4] = c1;
        *(uint4*)&sWL[so0] = d0; *(uint4*)&sWL[so0 + 4] = d1;
    }
    __syncthreads();

    for (int c = 0; c < nk; c++) {
        const int sS = (c & 1) * SP;

        // prefetch chunk c+1 into registers
        uint4 pa0, pa1, pb0, pb1, pc0, pc1, pd0, pd1;
        const bool more = (c + 1 < nk);
        if (more) {
            int k2 = (c + 1) * 16;
            pa0 = __ldg((const uint4*)(gAH + k2));
            pa1 = __ldg((const uint4*)(gAH + k2 + 4));
            pb0 = __ldg((const uint4*)(gAL + k2));
            pb1 = __ldg((const uint4*)(gAL + k2 + 4));
            pc0 = __ldg((const uint4*)(gWH + k2));
            pc1 = __ldg((const uint4*)(gWH + k2 + 4));
            pd0 = __ldg((const uint4*)(gWL + k2));
            pd1 = __ldg((const uint4*)(gWL + k2 + 4));
        }

        // mma over stage: 2 k16 steps
#pragma unroll
        for (int ks = 0; ks < 2; ks++) {
            const int cc = ks * 8 + (lane & 3);
            uint32_t bh[4][2], bl[4][2];
#pragma unroll
            for (int ni = 0; ni < 4; ni++) {
                int br = (wn * 32 + ni * 8 + (lane >> 2)) * P2 + cc;
                bh[ni][0] = sWH[sS + br];
                bh[ni][1] = sWH[sS + br + 4];
                bl[ni][0] = sWL[sS + br];
                bl[ni][1] = sWL[sS + br + 4];
            }
#pragma unroll
            for (int mi = 0; mi < 4; mi++) {
                int ar0 = (wm * 64 + mi * 16 + (lane >> 2)) * P2 + cc;
                int ar1 = ar0 + 8 * P2;
                uint32_t ah[4], al[4];
                ah[0] = sAH[sS + ar0]; ah[1] = sAH[sS + ar1];
                ah[2] = sAH[sS + ar0 + 4]; ah[3] = sAH[sS + ar1 + 4];
                al[0] = sAL[sS + ar0]; al[1] = sAL[sS + ar1];
                al[2] = sAL[sS + ar0 + 4]; al[3] = sAL[sS + ar1 + 4];
#pragma unroll
                for (int ni = 0; ni < 4; ni++) {
                    mma16(acc [mi][ni], ah, bh[ni]);
                    mma16(acc2[mi][ni], ah, bl[ni]);
                    mma16(acc2[mi][ni], al, bh[ni]);
                }
            }
        }

        if (more) {
            __syncthreads();
            const int so = so0 + ((c & 1) ^ 1) * SP;
            *(uint4*)&sAH[so] = pa0; *(uint4*)&sAH[so + 4] = pa1;
            *(uint4*)&sAL[so] = pb0; *(uint4*)&sAL[so + 4] = pb1;
            *(uint4*)&sWH[so] = pc0; *(uint4*)&sWH[so + 4] = pc1;
            *(uint4*)&sWL[so] = pd0; *(uint4*)&sWL[so + 4] = pd1;
            __syncthreads();
        }
    }

    // epilogue: v = acc + acc2/2048 (+bias); optional stats / split-out / MSE
    float lsum = 0.f;
    float sc[4][2], ssc[4][2];
#pragma unroll
    for (int ni = 0; ni < 4; ni++) { sc[ni][0] = sc[ni][1] = 0.f; ssc[ni][0] = ssc[ni][1] = 0.f; }

#pragma unroll
    for (int mi = 0; mi < 4; mi++) {
#pragma unroll
        for (int h = 0; h < 2; h++) {
            const size_t m = (size_t)(m0 + wm * 64 + mi * 16 + (lane >> 2) + h * 8);
#pragma unroll
            for (int ni = 0; ni < 4; ni++) {
                const int col = n0 + wn * 32 + ni * 8 + 2 * (lane & 3);
                float v0 = acc[mi][ni][2 * h + 0] + acc2[mi][ni][2 * h + 0] * INV2048;
                float v1 = acc[mi][ni][2 * h + 1] + acc2[mi][ni][2 * h + 1] * INV2048;
                if (bias) { v0 += __ldg(bias + col); v1 += __ldg(bias + col + 1); }
                if (statSum) {
                    sc[ni][0] += v0; ssc[ni][0] += v0 * v0;
                    sc[ni][1] += v1; ssc[ni][1] += v1 * v1;
                }
                if (ref) {
                    float d0 = v0 - __ldg(ref + m * ldc + col);
                    float d1 = v1 - __ldg(ref + m * ldc + col + 1);
                    lsum += d0 * d0 + d1 * d1;
                }
                *(float2*)(C + m * ldc + col) = make_float2(v0, v1);
                if (CH) {
                    uint32_t hh, ll;
                    split2h(v0, v1, hh, ll);
                    size_t o2 = m * ldc2 + (size_t)(((size_t)q * cQ ? 0 : 0) + (col >> 1));
                    // note: split-out never used with q-batching; col>>1 indexes half2
                    CH[o2] = hh; CL[o2] = ll;
                }
            }
        }
    }
    if (statSum) {
#pragma unroll
        for (int ni = 0; ni < 4; ni++) {
            float s0 = sc[ni][0], s1 = sc[ni][1], q0 = ssc[ni][0], q1 = ssc[ni][1];
#pragma unroll
            for (int off = 4; off < 32; off <<= 1) {
                s0 += __shfl_down_sync(0xffffffffu, s0, off);
                s1 += __shfl_down_sync(0xffffffffu, s1, off);
                q0 += __shfl_down_sync(0xffffffffu, q0, off);
                q1 += __shfl_down_sync(0xffffffffu, q1, off);
            }
            if (lane < 4) {
                int col = n0 + wn * 32 + ni * 8 + 2 * lane;
                atomicAdd(&statSum[col],       s0);
                atomicAdd(&statSum[col + 1],   s1);
                atomicAdd(&statSumsq[col],     q0);
                atomicAdd(&statSumsq[col + 1], q1);
            }
        }
    }
    if (lossAcc) {
#pragma unroll
        for (int off = 16; off; off >>= 1)
            lsum += __shfl_down_sync(0xffffffffu, lsum, off);
        if (lane == 0) s_red[wid] = lsum;
        __syncthreads();
        if (tid == 0) {
            float s = 0.f;
#pragma unroll
            for (int w = 0; w < 8; w++) s += s_red[w];
            atomicAdd(lossAcc, s);
        }
    }
}

// ---------------- transpose ----------------
__global__ void transpose_kernel(const float* __restrict__ x, float* __restrict__ xt) {
    __shared__ float tile[32][33];
    int b  = blockIdx.z;
    int t0 = blockIdx.x * 32;
    int d0 = blockIdx.y * 32;
    int tx = threadIdx.x, ty = threadIdx.y;
    const float* xb = x  + (size_t)b * DIMV * TT;
    float*      xtb = xt + (size_t)b * TT * DIMV;
#pragma unroll
    for (int j = 0; j < 32; j += 8)
        tile[ty + j][tx] = xb[(size_t)(d0 + ty + j) * TT + t0 + tx];
    __syncthreads();
#pragma unroll
    for (int j = 0; j < 32; j += 8)
        xtb[(size_t)(t0 + ty + j) * DIMV + d0 + tx] = tile[tx][ty + j];
}

// ---------------- BN kernels ----------------
__global__ void colstats_kernel(const float* __restrict__ X, int N,
                                float* __restrict__ sum, float* __restrict__ sumsq) {
    int col = blockIdx.x * 32 + threadIdx.x;
    int r0  = blockIdx.y * 2048;
    float s = 0.f, ss = 0.f;
    for (int r = r0 + threadIdx.y; r < r0 + 2048; r += 8) {
        float v = X[(size_t)r * N + col];
        s += v; ss += v * v;
    }
    __shared__ float sh [8][32];
    __shared__ float sh2[8][32];
    sh [threadIdx.y][threadIdx.x] = s;
    sh2[threadIdx.y][threadIdx.x] = ss;
    __syncthreads();
    if (threadIdx.y == 0) {
#pragma unroll
        for (int w = 1; w < 8; w++) { s += sh[w][threadIdx.x]; ss += sh2[w][threadIdx.x]; }
        atomicAdd(&sum[col], s);
        atomicAdd(&sumsq[col], ss);
    }
}

__global__ void bnparams_kernel(const float* __restrict__ sum, const float* __restrict__ sumsq,
                                const float* __restrict__ g, const float* __restrict__ be, int N) {
    int c = blockIdx.x * 128 + threadIdx.x;
    if (c >= N) return;
    const float invM = 1.0f / (float)MROWS;
    float m   = sum[c] * invM;
    float var = sumsq[c] * invM - m * m;
    float sc  = g[c] * rsqrtf(var + 1e-5f);
    g_scale[c] = sc;
    g_shift[c] = be[c] - m * sc;
}

// apply BN (+relu) and emit split halves directly
__global__ void bnapply_split(const float* __restrict__ X,
                              uint32_t* __restrict__ H, uint32_t* __restrict__ L,
                              int mask, int relu) {
    size_t i = (size_t)blockIdx.x * 256 + threadIdx.x;
    float2 v = *(const float2*)(X + 2 * i);
    int c0 = (int)(2 * i) & mask;
    float a = v.x * g_scale[c0] + g_shift[c0];
    float b = v.y * g_scale[c0 + 1] + g_shift[c0 + 1];
    if (relu) { a = fmaxf(a, 0.f); b = fmaxf(b, 0.f); }
    uint32_t h, l;
    split2h(a, b, h, l);
    H[i] = h; L[i] = l;
}

// ---------------- gumbel ----------------
__device__ __forceinline__ float gumbel_of(float uu) {
    uu = fminf(fmaxf(uu, 1e-9f), 1.0f);
    return -logf(-logf(uu) + 1e-20f);
}

// ---------------- dual argmax with exact fp32 refinement ----------------
__global__ __launch_bounds__(256) void argmax_kernel(
    const float* __restrict__ logits, const float* __restrict__ z,
    const float* __restrict__ cb, const float* __restrict__ u,
    const float* __restrict__ lt, float* __restrict__ idx_out, int* __restrict__ code_out)
{
    const int q    = blockIdx.y;
    const int row  = blockIdx.x * 8 + (threadIdx.x >> 5);
    const int lane = threadIdx.x & 31;
    const float scale = expf(-__ldg(lt + q));
    const float* lrow = logits + ((size_t)q * MROWS + row) * CC;
    const float* urow = u + ((size_t)row * QQ + q) * CC;

    float lv[8], nn[8];
    bool exR[8], exN[8];
#pragma unroll
    for (int it = 0; it < 8; it++) {
        int c = it * 32 + lane;
        lv[it] = __ldg(lrow + c);
        nn[it] = lv[it] * scale + gumbel_of(__ldg(urow + c));
        exR[it] = false; exN[it] = false;
    }

    int candR[3], candN[3];
#pragma unroll
    for (int r = 0; r < 3; r++) {
        float bv = -INFINITY; int bi = 1 << 30;
#pragma unroll
        for (int it = 0; it < 8; it++)
            if (!exR[it] && (lv[it] > bv || (lv[it] == bv && it * 32 + lane < bi))) {
                bv = lv[it]; bi = it * 32 + lane;
            }
#pragma unroll
        for (int off = 16; off; off >>= 1) {
            float ov = __shfl_down_sync(0xffffffffu, bv, off);
            int   oi = __shfl_down_sync(0xffffffffu, bi, off);
            if (ov > bv || (ov == bv && oi < bi)) { bv = ov; bi = oi; }
        }
        bi = __shfl_sync(0xffffffffu, bi, 0);
        candR[r] = bi;
        if ((bi & 31) == lane) exR[bi >> 5] = true;

        bv = -INFINITY; bi = 1 << 30;
#pragma unroll
        for (int it = 0; it < 8; it++)
            if (!exN[it] && (nn[it] > bv || (nn[it] == bv && it * 32 + lane < bi))) {
                bv = nn[it]; bi = it * 32 + lane;
            }
#pragma unroll
        for (int off = 16; off; off >>= 1) {
            float ov = __shfl_down_sync(0xffffffffu, bv, off);
            int   oi = __shfl_down_sync(0xffffffffu, bi, off);
            if (ov > bv || (ov == bv && oi < bi)) { bv = ov; bi = oi; }
        }
        bi = __shfl_sync(0xffffffffu, bi, 0);
        candN[r] = bi;
        if ((bi & 31) == lane) exN[bi >> 5] = true;
    }

    const float* zrow = z + (size_t)row * (QQ * DD) + q * DD;
    float4 z0 = __ldg((const float4*)(zrow + lane * 8));
    float4 z1 = __ldg((const float4*)(zrow + lane * 8 + 4));
    float dR[3], dN[3];
#pragma unroll
    for (int r = 0; r < 3; r++) {
#pragma unroll
        for (int pass = 0; pass < 2; pass++) {
            int c = pass ? candN[r] : candR[r];
            const float* crow = cb + ((size_t)q * CC + c) * DD;
            float4 c0 = __ldg((const float4*)(crow + lane * 8));
            float4 c1 = __ldg((const float4*)(crow + lane * 8 + 4));
            float d = z0.x * c0.x + z0.y * c0.y + z0.z * c0.z + z0.w * c0.w
                    + z1.x * c1.x + z1.y * c1.y + z1.z * c1.z + z1.w * c1.w;
#pragma unroll
            for (int off = 16; off; off >>= 1)
                d += __shfl_down_sync(0xffffffffu, d, off);
            if (pass) dN[r] = d; else dR[r] = d;
        }
    }

    if (lane == 0) {
        int ri = candR[0]; float rv = dR[0];
#pragma unroll
        for (int r = 1; r < 3; r++)
            if (dR[r] > rv || (dR[r] == rv && candR[r] < ri)) { rv = dR[r]; ri = candR[r]; }
        int ni = candN[0];
        float nv = dN[0] * scale + gumbel_of(__ldg(urow + candN[0]));
#pragma unroll
        for (int r = 1; r < 3; r++) {
            float s = dN[r] * scale + gumbel_of(__ldg(urow + candN[r]));
            if (s > nv || (s == nv && candN[r] < ni)) { nv = s; ni = candN[r]; }
        }
        size_t o = (size_t)row * QQ + q;
        idx_out[o]  = (float)ri;
        code_out[o] = ni;
    }
}

// ---------------- embedding gather ----------------
__global__ void embed_kernel(const int* __restrict__ code, const float* __restrict__ cb,
                             float* __restrict__ emb) {
    int bt = blockIdx.x;
    int d  = threadIdx.x;
    float s = 0.f;
#pragma unroll
    for (int q = 0; q < QQ; q++) {
        int ci = code[bt * QQ + q];
        s += cb[((size_t)(q * CC + ci)) * DD + d];
    }
    emb[(size_t)bt * DD + d] = s;
}

__global__ void finalize_loss_kernel(float* __restrict__ out) {
    out[0] = g_loss[0] * (1.0f / (float)XR_N);
}

// ---------------- host orchestration ----------------
extern "C" void kernel_launch(void* const* d_in, const int* in_sizes, int n_in,
                              void* d_out, int out_size) {
    const float* x       = (const float*)d_in[0];
    const float* u       = (const float*)d_in[1];
    const float* cb      = (const float*)d_in[2];
    const float* lt      = (const float*)d_in[3];
    const float* enc_w0  = (const float*)d_in[4];
    const float* enc_b0  = (const float*)d_in[5];
    const float* enc_g0  = (const float*)d_in[6];
    const float* enc_be0 = (const float*)d_in[7];
    const float* enc_w1  = (const float*)d_in[8];
    const float* enc_b1  = (const float*)d_in[9];
    const float* enc_g1  = (const float*)d_in[10];
    const float* enc_be1 = (const float*)d_in[11];
    const float* enc_wo  = (const float*)d_in[12];
    const float* enc_bo  = (const float*)d_in[13];
    const float* dec_g   = (const float*)d_in[14];
    const float* dec_be  = (const float*)d_in[15];
    const float* dec_w0  = (const float*)d_in[16];
    const float* dec_b0  = (const float*)d_in[17];
    const float* dec_g0  = (const float*)d_in[18];
    const float* dec_be0 = (const float*)d_in[19];
    const float* dec_w1  = (const float*)d_in[20];
    const float* dec_b1  = (const float*)d_in[21];
    const float* dec_g1  = (const float*)d_in[22];
    const float* dec_be1 = (const float*)d_in[23];
    const float* fin_w   = (const float*)d_in[24];
    const float* fin_b   = (const float*)d_in[25];
    float* out = (float*)d_out;

    float *xt, *h0, *h1, *z, *logits, *emb, *sum, *sumsq, *loss;
    int* code;
    uint32_t *xtH, *xtL, *h0H, *h0L, *h1H, *h1L, *zH, *zL, *embH, *embL, *wH, *wL;
    cudaGetSymbolAddress((void**)&xt,    g_xt);
    cudaGetSymbolAddress((void**)&h0,    g_h0);
    cudaGetSymbolAddress((void**)&h1,    g_h1);
    cudaGetSymbolAddress((void**)&z,     g_z);
    cudaGetSymbolAddress((void**)&logits,g_logits);
    cudaGetSymbolAddress((void**)&emb,   g_emb);
    cudaGetSymbolAddress((void**)&code,  g_code);
    cudaGetSymbolAddress((void**)&sum,   g_sum);
    cudaGetSymbolAddress((void**)&sumsq, g_sumsq);
    cudaGetSymbolAddress((void**)&loss,  g_loss);
    cudaGetSymbolAddress((void**)&xtH,   g_xtH);   cudaGetSymbolAddress((void**)&xtL, g_xtL);
    cudaGetSymbolAddress((void**)&h0H,   g_h0H);   cudaGetSymbolAddress((void**)&h0L, g_h0L);
    cudaGetSymbolAddress((void**)&h1H,   g_h1H);   cudaGetSymbolAddress((void**)&h1L, g_h1L);
    cudaGetSymbolAddress((void**)&zH,    g_zH);    cudaGetSymbolAddress((void**)&zL,  g_zL);
    cudaGetSymbolAddress((void**)&embH,  g_embH);  cudaGetSymbolAddress((void**)&embL,g_embL);
    cudaGetSymbolAddress((void**)&wH,    g_wH);    cudaGetSymbolAddress((void**)&wL,  g_wL);

    cudaFuncSetAttribute(gemm_h, cudaFuncAttributeMaxDynamicSharedMemorySize, GSMEM2);

    // ---- pre-split weights + codebook ----
    split_mat<<<1024, 256>>>(enc_w0, wH + OFF_W0,  wL + OFF_W0);
    split_mat<<<2048, 256>>>(enc_w1, wH + OFF_W1,  wL + OFF_W1);
    split_mat<<<4096, 256>>>(enc_wo, wH + OFF_WO,  wL + OFF_WO);
    split_mat<<<1024, 256>>>(cb,     wH + OFF_CB,  wL + OFF_CB);
    split_mat<<< 512, 256>>>(dec_w0, wH + OFF_DW0, wL + OFF_DW0);
    split_mat<<<2048, 256>>>(dec_w1, wH + OFF_DW1, wL + OFF_DW1);
    split_mat<<<1024, 256>>>(fin_w,  wH + OFF_FW,  wL + OFF_FW);

    // ---- encoder ----
    transpose_kernel<<<dim3(TT / 32, DIMV / 32, BB), dim3(32, 8)>>>(x, xt);
    split_mat<<<16384, 256>>>(xt, xtH, xtL);

    cudaMemsetAsync(sum, 0, HIDV * sizeof(float));
    cudaMemsetAsync(sumsq, 0, HIDV * sizeof(float));
    gemm_h<<<dim3(HIDV / 128, MROWS / 128), 256, GSMEM2>>>(
        xtH, xtL, DIMV / 2, 0, wH + OFF_W0, wL + OFF_W0, DIMV / 2, 0,
        enc_b0, h0, HIDV, 0, nullptr, nullptr, 0, DIMV, sum, sumsq, nullptr, nullptr);
    bnparams_kernel<<<HIDV / 128, 128>>>(sum, sumsq, enc_g0, enc_be0, HIDV);
    bnapply_split<<<(unsigned)((size_t)MROWS * HIDV / 512), 256>>>(h0, h0H, h0L, HIDV - 1, 1);

    cudaMemsetAsync(sum, 0, HIDV * sizeof(float));
    cudaMemsetAsync(sumsq, 0, HIDV * sizeof(float));
    gemm_h<<<dim3(HIDV / 128, MROWS / 128), 256, GSMEM2>>>(
        h0H, h0L, HIDV / 2, 0, wH + OFF_W1, wL + OFF_W1, HIDV / 2, 0,
        enc_b1, h1, HIDV, 0, nullptr, nullptr, 0, HIDV, sum, sumsq, nullptr, nullptr);
    bnparams_kernel<<<HIDV / 128, 128>>>(sum, sumsq, enc_g1, enc_be1, HIDV);
    bnapply_split<<<(unsigned)((size_t)MROWS * HIDV / 512), 256>>>(h1, h1H, h1L, HIDV - 1, 1);

    // enc_wo: fp32 z + split halves out
    gemm_h<<<dim3((QQ * DD) / 128, MROWS / 128), 256, GSMEM2>>>(
        h1H, h1L, HIDV / 2, 0, wH + OFF_WO, wL + OFF_WO, HIDV / 2, 0,
        enc_bo, z, QQ * DD, 0, zH, zL, QQ * DD / 2, HIDV, nullptr, nullptr, nullptr, nullptr);

    // ---- logits (per-q block-diagonal) + argmax + embed ----
    gemm_h<<<dim3(CC / 128, MROWS / 128, QQ), 256, GSMEM2>>>(
        zH, zL, QQ * DD / 2, DD / 2,
        wH + OFF_CB, wL + OFF_CB, DD / 2, (long long)CC * DD / 2,
        nullptr, logits, CC, (long long)MROWS * CC,
        nullptr, nullptr, 0, DD, nullptr, nullptr, nullptr, nullptr);
    argmax_kernel<<<dim3(MROWS / 8, QQ), 256>>>(logits, z, cb, u, lt, out + XR_N, code);
    embed_kernel<<<MROWS, DD>>>(code, cb, emb);

    // ---- decoder ----
    cudaMemsetAsync(sum, 0, DD * sizeof(float));
    cudaMemsetAsync(sumsq, 0, DD * sizeof(float));
    colstats_kernel<<<dim3(DD / 32, 8), dim3(32, 8)>>>(emb, DD, sum, sumsq);
    bnparams_kernel<<<DD / 128, 128>>>(sum, sumsq, dec_g, dec_be, DD);
    bnapply_split<<<(unsigned)((size_t)MROWS * DD / 512), 256>>>(emb, embH, embL, DD - 1, 0);

    cudaMemsetAsync(sum, 0, HIDV * sizeof(float));
    cudaMemsetAsync(sumsq, 0, HIDV * sizeof(float));
    gemm_h<<<dim3(HIDV / 128, MROWS / 128), 256, GSMEM2>>>(
        embH, embL, DD / 2, 0, wH + OFF_DW0, wL + OFF_DW0, DD / 2, 0,
        dec_b0, h0, HIDV, 0, nullptr, nullptr, 0, DD, sum, sumsq, nullptr, nullptr);
    bnparams_kernel<<<HIDV / 128, 128>>>(sum, sumsq, dec_g0, dec_be0, HIDV);
    bnapply_split<<<(unsigned)((size_t)MROWS * HIDV / 512), 256>>>(h0, h0H, h0L, HIDV - 1, 1);

    cudaMemsetAsync(sum, 0, HIDV * sizeof(float));
    cudaMemsetAsync(sumsq, 0, HIDV * sizeof(float));
    gemm_h<<<dim3(HIDV / 128, MROWS / 128), 256, GSMEM2>>>(
        h0H, h0L, HIDV / 2, 0, wH + OFF_DW1, wL + OFF_DW1, HIDV / 2, 0,
        dec_b1, h1, HIDV, 0, nullptr, nullptr, 0, HIDV, sum, sumsq, nullptr, nullptr);
    bnparams_kernel<<<HIDV / 128, 128>>>(sum, sumsq, dec_g1, dec_be1, HIDV);
    bnapply_split<<<(unsigned)((size_t)MROWS * HIDV / 512), 256>>>(h1, h1H, h1L, HIDV - 1, 1);

    // ---- final linear + fused MSE loss vs xt ----
    cudaMemsetAsync(loss, 0, sizeof(float));
    gemm_h<<<dim3(DIMV / 128, MROWS / 128), 256, GSMEM2>>>(
        h1H, h1L, HIDV / 2, 0, wH + OFF_FW, wL + OFF_FW, HIDV / 2, 0,
        fin_b, out, DIMV, 0, nullptr, nullptr, 0, HIDV, nullptr, nullptr, xt, loss);
    finalize_loss_kernel<<<1, 1>>>(out + XR_N + IDX_N);
}

// round 8
// speedup vs baseline: 2.3861x; 1.1714x over previous
#include <cuda_runtime.h>
#include <cuda_fp16.h>
#include <math.h>
#include <stdint.h>

// Problem constants
#define BB    32
#define TT    512
#define DIMV  512
#define QQ    8
#define CC    256
#define DD    256
#define HIDV  1024
#define MROWS (BB*TT)          // 16384
#define XR_N  (MROWS*DIMV)     // 8388608
#define IDX_N (MROWS*QQ)       // 131072

// ---------------- fp32 scratch ----------------
__device__ float g_xt [MROWS*DIMV];
__device__ float g_h0 [MROWS*HIDV];
__device__ float g_h1 [MROWS*HIDV];
__device__ float g_z  [MROWS*QQ*DD];
__device__ float g_logits[(size_t)QQ*MROWS*CC];
__device__ float g_emb[MROWS*DD];
__device__ int   g_code[MROWS*QQ];
__device__ float g_sum[2048];
__device__ float g_sumsq[2048];
__device__ float g_scale[2048];
__device__ float g_shift[2048];
__device__ float g_loss[1];

// ---------------- pre-split half2 buffers (u32 = 2 halves) ----------------
__device__ uint32_t g_xtH [MROWS*DIMV/2],  g_xtL [MROWS*DIMV/2];
__device__ uint32_t g_h0H [MROWS*HIDV/2],  g_h0L [MROWS*HIDV/2];
__device__ uint32_t g_h1H [MROWS*HIDV/2],  g_h1L [MROWS*HIDV/2];
__device__ uint32_t g_zH  [MROWS*QQ*DD/2], g_zL  [MROWS*QQ*DD/2];
__device__ uint32_t g_embH[MROWS*DD/2],    g_embL[MROWS*DD/2];
__device__ uint32_t g_wH  [3014656],       g_wL  [3014656];
// weight pool offsets (u32 units)
#define OFF_W0   0
#define OFF_W1   262144
#define OFF_WO   786432
#define OFF_CB   1835008
#define OFF_DW0  2097152
#define OFF_DW1  2228224
#define OFF_FW   2752512

// ======================= fp16x3 helpers =======================
#define INV2048 4.8828125e-4f

__device__ __forceinline__ void split2h(float a, float b, uint32_t& hi, uint32_t& lo) {
    __half ha = __float2half_rn(a), hb = __float2half_rn(b);
    float ra = (a - __half2float(ha)) * 2048.0f;
    float rb = (b - __half2float(hb)) * 2048.0f;
    __half2 h = __halves2half2(ha, hb);
    __half2 l = __halves2half2(__float2half_rn(ra), __float2half_rn(rb));
    hi = *(uint32_t*)&h;
    lo = *(uint32_t*)&l;
}

__device__ __forceinline__ void mma16(float* d, const uint32_t* a, const uint32_t* b) {
    asm volatile(
        "mma.sync.aligned.m16n8k16.row.col.f32.f16.f16.f32 "
        "{%0,%1,%2,%3}, {%4,%5,%6,%7}, {%8,%9}, {%0,%1,%2,%3};"
        : "+f"(d[0]), "+f"(d[1]), "+f"(d[2]), "+f"(d[3])
        : "r"(a[0]), "r"(a[1]), "r"(a[2]), "r"(a[3]), "r"(b[0]), "r"(b[1]));
}

__device__ __forceinline__ void ldsm4(uint32_t& r0, uint32_t& r1, uint32_t& r2, uint32_t& r3,
                                      uint32_t addr) {
    asm volatile("ldmatrix.sync.aligned.m8n8.x4.shared.b16 {%0,%1,%2,%3}, [%4];"
                 : "=r"(r0), "=r"(r1), "=r"(r2), "=r"(r3) : "r"(addr));
}

// ---------------- generic fp32 -> hi/lo split ----------------
__global__ void split_mat(const float* __restrict__ X,
                          uint32_t* __restrict__ H, uint32_t* __restrict__ L) {
    size_t i = (size_t)blockIdx.x * 256 + threadIdx.x;
    float2 v = *(const float2*)(X + 2 * i);
    uint32_t h, l;
    split2h(v.x, v.y, h, l);
    H[i] = h; L[i] = l;
}

// ======================= pre-split fp16x3 GEMM (ldmatrix + 3-pass mma) =======================
#define KC    32
#define P2    20
#define SP    (128*P2)
#define GSMEM2 (8*SP*4)          // 81920 bytes

__global__ __launch_bounds__(256, 1)
void gemm_h(const uint32_t* __restrict__ AH, const uint32_t* __restrict__ AL,
            int lda2, long long aQ2,
            const uint32_t* __restrict__ WH, const uint32_t* __restrict__ WL,
            int ldw2, long long wQ2,
            const float* __restrict__ bias,
            float* __restrict__ C, int ldc, long long cQ,
            uint32_t* __restrict__ CH, uint32_t* __restrict__ CL, int ldc2,
            int K,
            float* __restrict__ statSum, float* __restrict__ statSumsq,
            const float* __restrict__ ref, float* __restrict__ lossAcc)
{
    extern __shared__ uint32_t smu[];
    __shared__ float s_red[8];

    const int tid  = threadIdx.x;
    const int lane = tid & 31;
    const int wid  = tid >> 5;
    const int wm   = wid >> 2;
    const int wn   = wid & 3;
    const int m0   = blockIdx.y * 128;
    const int n0   = blockIdx.x * 128;
    const int q    = blockIdx.z;
    AH += (size_t)q * aQ2;  AL += (size_t)q * aQ2;
    WH += (size_t)q * wQ2;  WL += (size_t)q * wQ2;
    C  += (size_t)q * cQ;

    uint32_t* sAH = smu;               // [2][SP]
    uint32_t* sAL = smu + 2 * SP;
    uint32_t* sWH = smu + 4 * SP;
    uint32_t* sWL = smu + 6 * SP;

    const int row = tid >> 1;          // staging row 0..127
    const int kb8 = (tid & 1) * 8;     // staging u32-half (0 or 8)

    // ldmatrix lane addressing (byte offsets into smem)
    const uint32_t smemBase = (uint32_t)__cvta_generic_to_shared(smu);
    const int g  = lane >> 3;
    const int lr = lane & 7;
    const uint32_t aOff = ((uint32_t)((wm * 64 + (g & 1) * 8 + lr) * P2 + (g >> 1) * 4)) * 4;
    const uint32_t bOff = ((uint32_t)(4 * SP + (wn * 32 + (g >> 1) * 8 + lr) * P2 + (g & 1) * 4)) * 4;

    float acc [4][4][4];
    float acc2[4][4][4];
#pragma unroll
    for (int i = 0; i < 4; i++)
#pragma unroll
        for (int j = 0; j < 4; j++)
#pragma unroll
            for (int r = 0; r < 4; r++) { acc[i][j][r] = 0.f; acc2[i][j][r] = 0.f; }

    const int nk = K / KC;             // chunk = 16 u32 per row

    const uint32_t* gAH = AH + (size_t)(m0 + row) * lda2 + kb8;
    const uint32_t* gAL = AL + (size_t)(m0 + row) * lda2 + kb8;
    const uint32_t* gWH = WH + (size_t)(n0 + row) * ldw2 + kb8;
    const uint32_t* gWL = WL + (size_t)(n0 + row) * ldw2 + kb8;
    const int so0 = row * P2 + kb8;

    // prologue: stage chunk 0 into stage 0
    {
        uint4 a0 = __ldg((const uint4*)(gAH));
        uint4 a1 = __ldg((const uint4*)(gAH + 4));
        uint4 b0 = __ldg((const uint4*)(gAL));
        uint4 b1 = __ldg((const uint4*)(gAL + 4));
        uint4 c0 = __ldg((const uint4*)(gWH));
        uint4 c1 = __ldg((const uint4*)(gWH + 4));
        uint4 d0 = __ldg((const uint4*)(gWL));
        uint4 d1 = __ldg((const uint4*)(gWL + 4));
        *(uint4*)&sAH[so0] = a0; *(uint4*)&sAH[so0 + 4] = a1;
        *(uint4*)&sAL[so0] = b0; *(uint4*)&sAL[so0 + 4] = b1;
        *(uint4*)&sWH[so0] = c0; *(uint4*)&sWH[so0 + 4] = c1;
        *(uint4*)&sWL[so0] = d0; *(uint4*)&sWL[so0 + 4] = d1;
    }
    __syncthreads();

    for (int c = 0; c < nk; c++) {
        const uint32_t sS4 = (uint32_t)((c & 1) * SP) * 4;

        // prefetch chunk c+1 into registers
        uint4 pa0, pa1, pb0, pb1, pc0, pc1, pd0, pd1;
        const bool more = (c + 1 < nk);
        if (more) {
            int k2 = (c + 1) * 16;
            pa0 = __ldg((const uint4*)(gAH + k2));
            pa1 = __ldg((const uint4*)(gAH + k2 + 4));
            pb0 = __ldg((const uint4*)(gAL + k2));
            pb1 = __ldg((const uint4*)(gAL + k2 + 4));
            pc0 = __ldg((const uint4*)(gWH + k2));
            pc1 = __ldg((const uint4*)(gWH + k2 + 4));
            pd0 = __ldg((const uint4*)(gWL + k2));
            pd1 = __ldg((const uint4*)(gWL + k2 + 4));
        }

        // mma over stage: 2 k16 steps, ldmatrix fragments + 3 dependency-free passes
#pragma unroll
        for (int ks = 0; ks < 2; ks++) {
            uint32_t ah[4][4], al[4][4], bh[4][2], bl[4][2];
            const uint32_t aA = smemBase + aOff + sS4 + ks * 32;
            const uint32_t bA = smemBase + bOff + sS4 + ks * 32;
#pragma unroll
            for (int mi = 0; mi < 4; mi++) {
                ldsm4(ah[mi][0], ah[mi][1], ah[mi][2], ah[mi][3], aA + mi * (16 * P2 * 4));
                ldsm4(al[mi][0], al[mi][1], al[mi][2], al[mi][3],
                      aA + mi * (16 * P2 * 4) + 2 * SP * 4);
            }
#pragma unroll
            for (int p = 0; p < 2; p++) {
                ldsm4(bh[p * 2][0], bh[p * 2][1], bh[p * 2 + 1][0], bh[p * 2 + 1][1],
                      bA + p * (16 * P2 * 4));
                ldsm4(bl[p * 2][0], bl[p * 2][1], bl[p * 2 + 1][0], bl[p * 2 + 1][1],
                      bA + p * (16 * P2 * 4) + 2 * SP * 4);
            }
            // pass 1: hi*hi -> acc (16 distinct accumulators)
#pragma unroll
            for (int mi = 0; mi < 4; mi++)
#pragma unroll
                for (int ni = 0; ni < 4; ni++)
                    mma16(acc[mi][ni], ah[mi], bh[ni]);
            // pass 2: hi*lo -> acc2
#pragma unroll
            for (int mi = 0; mi < 4; mi++)
#pragma unroll
                for (int ni = 0; ni < 4; ni++)
                    mma16(acc2[mi][ni], ah[mi], bl[ni]);
            // pass 3: lo*hi -> acc2 (reuse distance 16)
#pragma unroll
            for (int mi = 0; mi < 4; mi++)
#pragma unroll
                for (int ni = 0; ni < 4; ni++)
                    mma16(acc2[mi][ni], al[mi], bh[ni]);
        }

        if (more) {
            __syncthreads();
            const int so = so0 + ((c & 1) ^ 1) * SP;
            *(uint4*)&sAH[so] = pa0; *(uint4*)&sAH[so + 4] = pa1;
            *(uint4*)&sAL[so] = pb0; *(uint4*)&sAL[so + 4] = pb1;
            *(uint4*)&sWH[so] = pc0; *(uint4*)&sWH[so + 4] = pc1;
            *(uint4*)&sWL[so] = pd0; *(uint4*)&sWL[so + 4] = pd1;
            __syncthreads();
        }
    }

    // epilogue: v = acc + acc2/2048 (+bias); optional stats / split-out / MSE
    float lsum = 0.f;
    float sc[4][2], ssc[4][2];
#pragma unroll
    for (int ni = 0; ni < 4; ni++) { sc[ni][0] = sc[ni][1] = 0.f; ssc[ni][0] = ssc[ni][1] = 0.f; }

#pragma unroll
    for (int mi = 0; mi < 4; mi++) {
#pragma unroll
        for (int h = 0; h < 2; h++) {
            const size_t m = (size_t)(m0 + wm * 64 + mi * 16 + (lane >> 2) + h * 8);
#pragma unroll
            for (int ni = 0; ni < 4; ni++) {
                const int col = n0 + wn * 32 + ni * 8 + 2 * (lane & 3);
                float v0 = acc[mi][ni][2 * h + 0] + acc2[mi][ni][2 * h + 0] * INV2048;
                float v1 = acc[mi][ni][2 * h + 1] + acc2[mi][ni][2 * h + 1] * INV2048;
                if (bias) { v0 += __ldg(bias + col); v1 += __ldg(bias + col + 1); }
                if (statSum) {
                    sc[ni][0] += v0; ssc[ni][0] += v0 * v0;
                    sc[ni][1] += v1; ssc[ni][1] += v1 * v1;
                }
                if (ref) {
                    float d0 = v0 - __ldg(ref + m * ldc + col);
                    float d1 = v1 - __ldg(ref + m * ldc + col + 1);
                    lsum += d0 * d0 + d1 * d1;
                }
                *(float2*)(C + m * ldc + col) = make_float2(v0, v1);
                if (CH) {
                    uint32_t hh, ll;
                    split2h(v0, v1, hh, ll);
                    size_t o2 = m * ldc2 + (size_t)(col >> 1);
                    CH[o2] = hh; CL[o2] = ll;
                }
            }
        }
    }
    if (statSum) {
#pragma unroll
        for (int ni = 0; ni < 4; ni++) {
            float s0 = sc[ni][0], s1 = sc[ni][1], q0 = ssc[ni][0], q1 = ssc[ni][1];
#pragma unroll
            for (int off = 4; off < 32; off <<= 1) {
                s0 += __shfl_down_sync(0xffffffffu, s0, off);
                s1 += __shfl_down_sync(0xffffffffu, s1, off);
                q0 += __shfl_down_sync(0xffffffffu, q0, off);
                q1 += __shfl_down_sync(0xffffffffu, q1, off);
            }
            if (lane < 4) {
                int col = n0 + wn * 32 + ni * 8 + 2 * lane;
                atomicAdd(&statSum[col],       s0);
                atomicAdd(&statSum[col + 1],   s1);
                atomicAdd(&statSumsq[col],     q0);
                atomicAdd(&statSumsq[col + 1], q1);
            }
        }
    }
    if (lossAcc) {
#pragma unroll
        for (int off = 16; off; off >>= 1)
            lsum += __shfl_down_sync(0xffffffffu, lsum, off);
        if (lane == 0) s_red[wid] = lsum;
        __syncthreads();
        if (tid == 0) {
            float s = 0.f;
#pragma unroll
            for (int w = 0; w < 8; w++) s += s_red[w];
            atomicAdd(lossAcc, s);
        }
    }
}

// ---------------- transpose ----------------
__global__ void transpose_kernel(const float* __restrict__ x, float* __restrict__ xt) {
    __shared__ float tile[32][33];
    int b  = blockIdx.z;
    int t0 = blockIdx.x * 32;
    int d0 = blockIdx.y * 32;
    int tx = threadIdx.x, ty = threadIdx.y;
    const float* xb = x  + (size_t)b * DIMV * TT;
    float*      xtb = xt + (size_t)b * TT * DIMV;
#pragma unroll
    for (int j = 0; j < 32; j += 8)
        tile[ty + j][tx] = xb[(size_t)(d0 + ty + j) * TT + t0 + tx];
    __syncthreads();
#pragma unroll
    for (int j = 0; j < 32; j += 8)
        xtb[(size_t)(t0 + ty + j) * DIMV + d0 + tx] = tile[tx][ty + j];
}

// ---------------- BN kernels ----------------
__global__ void colstats_kernel(const float* __restrict__ X, int N,
                                float* __restrict__ sum, float* __restrict__ sumsq) {
    int col = blockIdx.x * 32 + threadIdx.x;
    int r0  = blockIdx.y * 2048;
    float s = 0.f, ss = 0.f;
    for (int r = r0 + threadIdx.y; r < r0 + 2048; r += 8) {
        float v = X[(size_t)r * N + col];
        s += v; ss += v * v;
    }
    __shared__ float sh [8][32];
    __shared__ float sh2[8][32];
    sh [threadIdx.y][threadIdx.x] = s;
    sh2[threadIdx.y][threadIdx.x] = ss;
    __syncthreads();
    if (threadIdx.y == 0) {
#pragma unroll
        for (int w = 1; w < 8; w++) { s += sh[w][threadIdx.x]; ss += sh2[w][threadIdx.x]; }
        atomicAdd(&sum[col], s);
        atomicAdd(&sumsq[col], ss);
    }
}

__global__ void bnparams_kernel(const float* __restrict__ sum, const float* __restrict__ sumsq,
                                const float* __restrict__ g, const float* __restrict__ be, int N) {
    int c = blockIdx.x * 128 + threadIdx.x;
    if (c >= N) return;
    const float invM = 1.0f / (float)MROWS;
    float m   = sum[c] * invM;
    float var = sumsq[c] * invM - m * m;
    float sc  = g[c] * rsqrtf(var + 1e-5f);
    g_scale[c] = sc;
    g_shift[c] = be[c] - m * sc;
}

// apply BN (+relu) and emit split halves directly
__global__ void bnapply_split(const float* __restrict__ X,
                              uint32_t* __restrict__ H, uint32_t* __restrict__ L,
                              int mask, int relu) {
    size_t i = (size_t)blockIdx.x * 256 + threadIdx.x;
    float2 v = *(const float2*)(X + 2 * i);
    int c0 = (int)(2 * i) & mask;
    float a = v.x * g_scale[c0] + g_shift[c0];
    float b = v.y * g_scale[c0 + 1] + g_shift[c0 + 1];
    if (relu) { a = fmaxf(a, 0.f); b = fmaxf(b, 0.f); }
    uint32_t h, l;
    split2h(a, b, h, l);
    H[i] = h; L[i] = l;
}

// ---------------- gumbel ----------------
__device__ __forceinline__ float gumbel_of(float uu) {
    uu = fminf(fmaxf(uu, 1e-9f), 1.0f);
    return -logf(-logf(uu) + 1e-20f);
}

// ---------------- dual argmax with exact fp32 refinement ----------------
__global__ __launch_bounds__(256) void argmax_kernel(
    const float* __restrict__ logits, const float* __restrict__ z,
    const float* __restrict__ cb, const float* __restrict__ u,
    const float* __restrict__ lt, float* __restrict__ idx_out, int* __restrict__ code_out)
{
    const int q    = blockIdx.y;
    const int row  = blockIdx.x * 8 + (threadIdx.x >> 5);
    const int lane = threadIdx.x & 31;
    const float scale = expf(-__ldg(lt + q));
    const float* lrow = logits + ((size_t)q * MROWS + row) * CC;
    const float* urow = u + ((size_t)row * QQ + q) * CC;

    float lv[8], nn[8];
    bool exR[8], exN[8];
#pragma unroll
    for (int it = 0; it < 8; it++) {
        int c = it * 32 + lane;
        lv[it] = __ldg(lrow + c);
        nn[it] = lv[it] * scale + gumbel_of(__ldg(urow + c));
        exR[it] = false; exN[it] = false;
    }

    int candR[3], candN[3];
#pragma unroll
    for (int r = 0; r < 3; r++) {
        float bv = -INFINITY; int bi = 1 << 30;
#pragma unroll
        for (int it = 0; it < 8; it++)
            if (!exR[it] && (lv[it] > bv || (lv[it] == bv && it * 32 + lane < bi))) {
                bv = lv[it]; bi = it * 32 + lane;
            }
#pragma unroll
        for (int off = 16; off; off >>= 1) {
            float ov = __shfl_down_sync(0xffffffffu, bv, off);
            int   oi = __shfl_down_sync(0xffffffffu, bi, off);
            if (ov > bv || (ov == bv && oi < bi)) { bv = ov; bi = oi; }
        }
        bi = __shfl_sync(0xffffffffu, bi, 0);
        candR[r] = bi;
        if ((bi & 31) == lane) exR[bi >> 5] = true;

        bv = -INFINITY; bi = 1 << 30;
#pragma unroll
        for (int it = 0; it < 8; it++)
            if (!exN[it] && (nn[it] > bv || (nn[it] == bv && it * 32 + lane < bi))) {
                bv = nn[it]; bi = it * 32 + lane;
            }
#pragma unroll
        for (int off = 16; off; off >>= 1) {
            float ov = __shfl_down_sync(0xffffffffu, bv, off);
            int   oi = __shfl_down_sync(0xffffffffu, bi, off);
            if (ov > bv || (ov == bv && oi < bi)) { bv = ov; bi = oi; }
        }
        bi = __shfl_sync(0xffffffffu, bi, 0);
        candN[r] = bi;
        if ((bi & 31) == lane) exN[bi >> 5] = true;
    }

    const float* zrow = z + (size_t)row * (QQ * DD) + q * DD;
    float4 z0 = __ldg((const float4*)(zrow + lane * 8));
    float4 z1 = __ldg((const float4*)(zrow + lane * 8 + 4));
    float dR[3], dN[3];
#pragma unroll
    for (int r = 0; r < 3; r++) {
#pragma unroll
        for (int pass = 0; pass < 2; pass++) {
            int c = pass ? candN[r] : candR[r];
            const float* crow = cb + ((size_t)q * CC + c) * DD;
            float4 c0 = __ldg((const float4*)(crow + lane * 8));
            float4 c1 = __ldg((const float4*)(crow + lane * 8 + 4));
            float d = z0.x * c0.x + z0.y * c0.y + z0.z * c0.z + z0.w * c0.w
                    + z1.x * c1.x + z1.y * c1.y + z1.z * c1.z + z1.w * c1.w;
#pragma unroll
            for (int off = 16; off; off >>= 1)
                d += __shfl_down_sync(0xffffffffu, d, off);
            if (pass) dN[r] = d; else dR[r] = d;
        }
    }

    if (lane == 0) {
        int ri = candR[0]; float rv = dR[0];
#pragma unroll
        for (int r = 1; r < 3; r++)
            if (dR[r] > rv || (dR[r] == rv && candR[r] < ri)) { rv = dR[r]; ri = candR[r]; }
        int ni = candN[0];
        float nv = dN[0] * scale + gumbel_of(__ldg(urow + candN[0]));
#pragma unroll
        for (int r = 1; r < 3; r++) {
            float s = dN[r] * scale + gumbel_of(__ldg(urow + candN[r]));
            if (s > nv || (s == nv && candN[r] < ni)) { nv = s; ni = candN[r]; }
        }
        size_t o = (size_t)row * QQ + q;
        idx_out[o]  = (float)ri;
        code_out[o] = ni;
    }
}

// ---------------- embedding gather ----------------
__global__ void embed_kernel(const int* __restrict__ code, const float* __restrict__ cb,
                             float* __restrict__ emb) {
    int bt = blockIdx.x;
    int d  = threadIdx.x;
    float s = 0.f;
#pragma unroll
    for (int q = 0; q < QQ; q++) {
        int ci = code[bt * QQ + q];
        s += cb[((size_t)(q * CC + ci)) * DD + d];
    }
    emb[(size_t)bt * DD + d] = s;
}

__global__ void finalize_loss_kernel(float* __restrict__ out) {
    out[0] = g_loss[0] * (1.0f / (float)XR_N);
}

// ---------------- host orchestration ----------------
extern "C" void kernel_launch(void* const* d_in, const int* in_sizes, int n_in,
                              void* d_out, int out_size) {
    const float* x       = (const float*)d_in[0];
    const float* u       = (const float*)d_in[1];
    const float* cb      = (const float*)d_in[2];
    const float* lt      = (const float*)d_in[3];
    const float* enc_w0  = (const float*)d_in[4];
    const float* enc_b0  = (const float*)d_in[5];
    const float* enc_g0  = (const float*)d_in[6];
    const float* enc_be0 = (const float*)d_in[7];
    const float* enc_w1  = (const float*)d_in[8];
    const float* enc_b1  = (const float*)d_in[9];
    const float* enc_g1  = (const float*)d_in[10];
    const float* enc_be1 = (const float*)d_in[11];
    const float* enc_wo  = (const float*)d_in[12];
    const float* enc_bo  = (const float*)d_in[13];
    const float* dec_g   = (const float*)d_in[14];
    const float* dec_be  = (const float*)d_in[15];
    const float* dec_w0  = (const float*)d_in[16];
    const float* dec_b0  = (const float*)d_in[17];
    const float* dec_g0  = (const float*)d_in[18];
    const float* dec_be0 = (const float*)d_in[19];
    const float* dec_w1  = (const float*)d_in[20];
    const float* dec_b1  = (const float*)d_in[21];
    const float* dec_g1  = (const float*)d_in[22];
    const float* dec_be1 = (const float*)d_in[23];
    const float* fin_w   = (const float*)d_in[24];
    const float* fin_b   = (const float*)d_in[25];
    float* out = (float*)d_out;

    float *xt, *h0, *h1, *z, *logits, *emb, *sum, *sumsq, *loss;
    int* code;
    uint32_t *xtH, *xtL, *h0H, *h0L, *h1H, *h1L, *zH, *zL, *embH, *embL, *wH, *wL;
    cudaGetSymbolAddress((void**)&xt,    g_xt);
    cudaGetSymbolAddress((void**)&h0,    g_h0);
    cudaGetSymbolAddress((void**)&h1,    g_h1);
    cudaGetSymbolAddress((void**)&z,     g_z);
    cudaGetSymbolAddress((void**)&logits,g_logits);
    cudaGetSymbolAddress((void**)&emb,   g_emb);
    cudaGetSymbolAddress((void**)&code,  g_code);
    cudaGetSymbolAddress((void**)&sum,   g_sum);
    cudaGetSymbolAddress((void**)&sumsq, g_sumsq);
    cudaGetSymbolAddress((void**)&loss,  g_loss);
    cudaGetSymbolAddress((void**)&xtH,   g_xtH);   cudaGetSymbolAddress((void**)&xtL, g_xtL);
    cudaGetSymbolAddress((void**)&h0H,   g_h0H);   cudaGetSymbolAddress((void**)&h0L, g_h0L);
    cudaGetSymbolAddress((void**)&h1H,   g_h1H);   cudaGetSymbolAddress((void**)&h1L, g_h1L);
    cudaGetSymbolAddress((void**)&zH,    g_zH);    cudaGetSymbolAddress((void**)&zL,  g_zL);
    cudaGetSymbolAddress((void**)&embH,  g_embH);  cudaGetSymbolAddress((void**)&embL,g_embL);
    cudaGetSymbolAddress((void**)&wH,    g_wH);    cudaGetSymbolAddress((void**)&wL,  g_wL);

    cudaFuncSetAttribute(gemm_h, cudaFuncAttributeMaxDynamicSharedMemorySize, GSMEM2);

    // ---- pre-split weights + codebook ----
    split_mat<<<1024, 256>>>(enc_w0, wH + OFF_W0,  wL + OFF_W0);
    split_mat<<<2048, 256>>>(enc_w1, wH + OFF_W1,  wL + OFF_W1);
    split_mat<<<4096, 256>>>(enc_wo, wH + OFF_WO,  wL + OFF_WO);
    split_mat<<<1024, 256>>>(cb,     wH + OFF_CB,  wL + OFF_CB);
    split_mat<<< 512, 256>>>(dec_w0, wH + OFF_DW0, wL + OFF_DW0);
    split_mat<<<2048, 256>>>(dec_w1, wH + OFF_DW1, wL + OFF_DW1);
    split_mat<<<1024, 256>>>(fin_w,  wH + OFF_FW,  wL + OFF_FW);

    // ---- encoder ----
    transpose_kernel<<<dim3(TT / 32, DIMV / 32, BB), dim3(32, 8)>>>(x, xt);
    split_mat<<<16384, 256>>>(xt, xtH, xtL);

    cudaMemsetAsync(sum, 0, HIDV * sizeof(float));
    cudaMemsetAsync(sumsq, 0, HIDV * sizeof(float));
    gemm_h<<<dim3(HIDV / 128, MROWS / 128), 256, GSMEM2>>>(
        xtH, xtL, DIMV / 2, 0, wH + OFF_W0, wL + OFF_W0, DIMV / 2, 0,
        enc_b0, h0, HIDV, 0, nullptr, nullptr, 0, DIMV, sum, sumsq, nullptr, nullptr);
    bnparams_kernel<<<HIDV / 128, 128>>>(sum, sumsq, enc_g0, enc_be0, HIDV);
    bnapply_split<<<(unsigned)((size_t)MROWS * HIDV / 512), 256>>>(h0, h0H, h0L, HIDV - 1, 1);

    cudaMemsetAsync(sum, 0, HIDV * sizeof(float));
    cudaMemsetAsync(sumsq, 0, HIDV * sizeof(float));
    gemm_h<<<dim3(HIDV / 128, MROWS / 128), 256, GSMEM2>>>(
        h0H, h0L, HIDV / 2, 0, wH + OFF_W1, wL + OFF_W1, HIDV / 2, 0,
        enc_b1, h1, HIDV, 0, nullptr, nullptr, 0, HIDV, sum, sumsq, nullptr, nullptr);
    bnparams_kernel<<<HIDV / 128, 128>>>(sum, sumsq, enc_g1, enc_be1, HIDV);
    bnapply_split<<<(unsigned)((size_t)MROWS * HIDV / 512), 256>>>(h1, h1H, h1L, HIDV - 1, 1);

    // enc_wo: fp32 z + split halves out
    gemm_h<<<dim3((QQ * DD) / 128, MROWS / 128), 256, GSMEM2>>>(
        h1H, h1L, HIDV / 2, 0, wH + OFF_WO, wL + OFF_WO, HIDV / 2, 0,
        enc_bo, z, QQ * DD, 0, zH, zL, QQ * DD / 2, HIDV, nullptr, nullptr, nullptr, nullptr);

    // ---- logits (per-q block-diagonal) + argmax + embed ----
    gemm_h<<<dim3(CC / 128, MROWS / 128, QQ), 256, GSMEM2>>>(
        zH, zL, QQ * DD / 2, DD / 2,
        wH + OFF_CB, wL + OFF_CB, DD / 2, (long long)CC * DD / 2,
        nullptr, logits, CC, (long long)MROWS * CC,
        nullptr, nullptr, 0, DD, nullptr, nullptr, nullptr, nullptr);
    argmax_kernel<<<dim3(MROWS / 8, QQ), 256>>>(logits, z, cb, u, lt, out + XR_N, code);
    embed_kernel<<<MROWS, DD>>>(code, cb, emb);

    // ---- decoder ----
    cudaMemsetAsync(sum, 0, DD * sizeof(float));
    cudaMemsetAsync(sumsq, 0, DD * sizeof(float));
    colstats_kernel<<<dim3(DD / 32, 8), dim3(32, 8)>>>(emb, DD, sum, sumsq);
    bnparams_kernel<<<DD / 128, 128>>>(sum, sumsq, dec_g, dec_be, DD);
    bnapply_split<<<(unsigned)((size_t)MROWS * DD / 512), 256>>>(emb, embH, embL, DD - 1, 0);

    cudaMemsetAsync(sum, 0, HIDV * sizeof(float));
    cudaMemsetAsync(sumsq, 0, HIDV * sizeof(float));
    gemm_h<<<dim3(HIDV / 128, MROWS / 128), 256, GSMEM2>>>(
        embH, embL, DD / 2, 0, wH + OFF_DW0, wL + OFF_DW0, DD / 2, 0,
        dec_b0, h0, HIDV, 0, nullptr, nullptr, 0, DD, sum, sumsq, nullptr, nullptr);
    bnparams_kernel<<<HIDV / 128, 128>>>(sum, sumsq, dec_g0, dec_be0, HIDV);
    bnapply_split<<<(unsigned)((size_t)MROWS * HIDV / 512), 256>>>(h0, h0H, h0L, HIDV - 1, 1);

    cudaMemsetAsync(sum, 0, HIDV * sizeof(float));
    cudaMemsetAsync(sumsq, 0, HIDV * sizeof(float));
    gemm_h<<<dim3(HIDV / 128, MROWS / 128), 256, GSMEM2>>>(
        h0H, h0L, HIDV / 2, 0, wH + OFF_DW1, wL + OFF_DW1, HIDV / 2, 0,
        dec_b1, h1, HIDV, 0, nullptr, nullptr, 0, HIDV, sum, sumsq, nullptr, nullptr);
    bnparams_kernel<<<HIDV / 128, 128>>>(sum, sumsq, dec_g1, dec_be1, HIDV);
    bnapply_split<<<(unsigned)((size_t)MROWS * HIDV / 512), 256>>>(h1, h1H, h1L, HIDV - 1, 1);

    // ---- final linear + fused MSE loss vs xt ----
    cudaMemsetAsync(loss, 0, sizeof(float));
    gemm_h<<<dim3(DIMV / 128, MROWS / 128), 256, GSMEM2>>>(
        h1H, h1L, HIDV / 2, 0, wH + OFF_FW, wL + OFF_FW, HIDV / 2, 0,
        fin_b, out, DIMV, 0, nullptr, nullptr, 0, HIDV, nullptr, nullptr, xt, loss);
    finalize_loss_kernel<<<1, 1>>>(out + XR_N + IDX_N);
}

// round 9
// speedup vs baseline: 2.4383x; 1.0219x over previous
#include <cuda_runtime.h>
#include <cuda_fp16.h>
#include <math.h>
#include <stdint.h>

// Problem constants
#define BB    32
#define TT    512
#define DIMV  512
#define QQ    8
#define CC    256
#define DD    256
#define HIDV  1024
#define MROWS (BB*TT)          // 16384
#define XR_N  (MROWS*DIMV)     // 8388608
#define IDX_N (MROWS*QQ)       // 131072

// ---------------- fp32 scratch ----------------
__device__ float g_xt [MROWS*DIMV];
__device__ float g_h0 [MROWS*HIDV];
__device__ float g_h1 [MROWS*HIDV];
__device__ float g_z  [MROWS*QQ*DD];
__device__ float g_logits[(size_t)QQ*MROWS*CC];
__device__ float g_emb[MROWS*DD];
__device__ int   g_code[MROWS*QQ];
__device__ float g_sum[2048];
__device__ float g_sumsq[2048];
__device__ float g_scale[2048];
__device__ float g_shift[2048];
__device__ float g_loss[1];

// ---------------- pre-split half2 buffers (u32 = 2 halves) ----------------
__device__ uint32_t g_xtH [MROWS*DIMV/2],  g_xtL [MROWS*DIMV/2];
__device__ uint32_t g_h0H [MROWS*HIDV/2],  g_h0L [MROWS*HIDV/2];
__device__ uint32_t g_h1H [MROWS*HIDV/2],  g_h1L [MROWS*HIDV/2];
__device__ uint32_t g_zH  [MROWS*QQ*DD/2], g_zL  [MROWS*QQ*DD/2];
__device__ uint32_t g_embH[MROWS*DD/2],    g_embL[MROWS*DD/2];
__device__ uint32_t g_wH  [3014656],       g_wL  [3014656];
// weight pool offsets (u32 units)
#define OFF_W0   0
#define OFF_W1   262144
#define OFF_WO   786432
#define OFF_CB   1835008
#define OFF_DW0  2097152
#define OFF_DW1  2228224
#define OFF_FW   2752512

// ======================= fp16x3 helpers =======================
#define INV2048 4.8828125e-4f

__device__ __forceinline__ void split2h(float a, float b, uint32_t& hi, uint32_t& lo) {
    __half ha = __float2half_rn(a), hb = __float2half_rn(b);
    float ra = (a - __half2float(ha)) * 2048.0f;
    float rb = (b - __half2float(hb)) * 2048.0f;
    __half2 h = __halves2half2(ha, hb);
    __half2 l = __halves2half2(__float2half_rn(ra), __float2half_rn(rb));
    hi = *(uint32_t*)&h;
    lo = *(uint32_t*)&l;
}

__device__ __forceinline__ void mma16(float* d, const uint32_t* a, const uint32_t* b) {
    asm volatile(
        "mma.sync.aligned.m16n8k16.row.col.f32.f16.f16.f32 "
        "{%0,%1,%2,%3}, {%4,%5,%6,%7}, {%8,%9}, {%0,%1,%2,%3};"
        : "+f"(d[0]), "+f"(d[1]), "+f"(d[2]), "+f"(d[3])
        : "r"(a[0]), "r"(a[1]), "r"(a[2]), "r"(a[3]), "r"(b[0]), "r"(b[1]));
}

__device__ __forceinline__ void ldsm4(uint32_t& r0, uint32_t& r1, uint32_t& r2, uint32_t& r3,
                                      uint32_t addr) {
    asm volatile("ldmatrix.sync.aligned.m8n8.x4.shared.b16 {%0,%1,%2,%3}, [%4];"
                 : "=r"(r0), "=r"(r1), "=r"(r2), "=r"(r3) : "r"(addr));
}

__device__ __forceinline__ void cpasync16(uint32_t smem_addr, const uint32_t* gptr) {
    asm volatile("cp.async.cg.shared.global [%0], [%1], 16;"
                 :: "r"(smem_addr), "l"(gptr) : "memory");
}

// ---------------- generic fp32 -> hi/lo split ----------------
__global__ void split_mat(const float* __restrict__ X,
                          uint32_t* __restrict__ H, uint32_t* __restrict__ L) {
    size_t i = (size_t)blockIdx.x * 256 + threadIdx.x;
    float2 v = *(const float2*)(X + 2 * i);
    uint32_t h, l;
    split2h(v.x, v.y, h, l);
    H[i] = h; L[i] = l;
}

// ======================= pre-split fp16x3 GEMM (cp.async 3-stage) =======================
// Stage layout (stage-major): stage s at s*4*SP u32; within: AH | AL | WH | WL.
#define KC      32
#define P2      20
#define SP      (128*P2)          // 2560 u32 per buffer
#define STAGES  3
#define STAGE_U (4*SP)            // u32 per stage
#define GSMEM2  (STAGES*STAGE_U*4)   // 122880 bytes

__global__ __launch_bounds__(256, 1)
void gemm_h(const uint32_t* __restrict__ AH, const uint32_t* __restrict__ AL,
            int lda2, long long aQ2,
            const uint32_t* __restrict__ WH, const uint32_t* __restrict__ WL,
            int ldw2, long long wQ2,
            const float* __restrict__ bias,
            float* __restrict__ C, int ldc, long long cQ,
            uint32_t* __restrict__ CH, uint32_t* __restrict__ CL, int ldc2,
            int K,
            float* __restrict__ statSum, float* __restrict__ statSumsq,
            const float* __restrict__ ref, float* __restrict__ lossAcc)
{
    extern __shared__ uint32_t smu[];
    __shared__ float s_red[8];

    const int tid  = threadIdx.x;
    const int lane = tid & 31;
    const int wid  = tid >> 5;
    const int wm   = wid >> 2;
    const int wn   = wid & 3;
    const int m0   = blockIdx.y * 128;
    const int n0   = blockIdx.x * 128;
    const int q    = blockIdx.z;
    AH += (size_t)q * aQ2;  AL += (size_t)q * aQ2;
    WH += (size_t)q * wQ2;  WL += (size_t)q * wQ2;
    C  += (size_t)q * cQ;

    const int row = tid >> 1;          // staging row 0..127
    const int kb8 = (tid & 1) * 8;     // staging u32-half (0 or 8)

    const uint32_t smemBase = (uint32_t)__cvta_generic_to_shared(smu);
    // ldmatrix lane addressing (byte offsets within a stage)
    const int g  = lane >> 3;
    const int lr = lane & 7;
    const uint32_t aOff = ((uint32_t)((wm * 64 + (g & 1) * 8 + lr) * P2 + (g >> 1) * 4)) * 4;
    const uint32_t bOff = ((uint32_t)(2 * SP + (wn * 32 + (g >> 1) * 8 + lr) * P2 + (g & 1) * 4)) * 4;

    float acc [4][4][4];
    float acc2[4][4][4];
#pragma unroll
    for (int i = 0; i < 4; i++)
#pragma unroll
        for (int j = 0; j < 4; j++)
#pragma unroll
            for (int r = 0; r < 4; r++) { acc[i][j][r] = 0.f; acc2[i][j][r] = 0.f; }

    const int nk = K / KC;             // chunk = 16 u32 per row

    const uint32_t* gAH = AH + (size_t)(m0 + row) * lda2 + kb8;
    const uint32_t* gAL = AL + (size_t)(m0 + row) * lda2 + kb8;
    const uint32_t* gWH = WH + (size_t)(n0 + row) * ldw2 + kb8;
    const uint32_t* gWL = WL + (size_t)(n0 + row) * ldw2 + kb8;
    const uint32_t stOff = (uint32_t)(row * P2 + kb8) * 4;   // byte offset within buffer

    // issue async stage for chunk c into stage c%STAGES (8x 16B per thread + commit)
    auto stage_chunk = [&](int c) {
        const int k2 = c * 16;
        const uint32_t sb = smemBase + (uint32_t)((c % STAGES) * STAGE_U) * 4 + stOff;
        cpasync16(sb,                 gAH + k2);
        cpasync16(sb + 16,            gAH + k2 + 4);
        cpasync16(sb + SP * 4,        gAL + k2);
        cpasync16(sb + SP * 4 + 16,   gAL + k2 + 4);
        cpasync16(sb + 2 * SP * 4,      gWH + k2);
        cpasync16(sb + 2 * SP * 4 + 16, gWH + k2 + 4);
        cpasync16(sb + 3 * SP * 4,      gWL + k2);
        cpasync16(sb + 3 * SP * 4 + 16, gWL + k2 + 4);
        asm volatile("cp.async.commit_group;" ::: "memory");
    };

    stage_chunk(0);
    if (nk > 1) stage_chunk(1);

    for (int c = 0; c < nk; c++) {
        // wait until chunk c's group is complete (allow 1 pending if one was issued beyond)
        if (c < nk - 1) asm volatile("cp.async.wait_group 1;" ::: "memory");
        else            asm volatile("cp.async.wait_group 0;" ::: "memory");
        __syncthreads();

        const uint32_t sb4 = (uint32_t)((c % STAGES) * STAGE_U) * 4;

#pragma unroll
        for (int ks = 0; ks < 2; ks++) {
            uint32_t ah[4][4], al[4][4], bh[4][2], bl[4][2];
            const uint32_t aA = smemBase + sb4 + aOff + ks * 32;
            const uint32_t bA = smemBase + sb4 + bOff + ks * 32;
#pragma unroll
            for (int mi = 0; mi < 4; mi++) {
                ldsm4(ah[mi][0], ah[mi][1], ah[mi][2], ah[mi][3], aA + mi * (16 * P2 * 4));
                ldsm4(al[mi][0], al[mi][1], al[mi][2], al[mi][3],
                      aA + mi * (16 * P2 * 4) + SP * 4);
            }
#pragma unroll
            for (int p = 0; p < 2; p++) {
                ldsm4(bh[p * 2][0], bh[p * 2][1], bh[p * 2 + 1][0], bh[p * 2 + 1][1],
                      bA + p * (16 * P2 * 4));
                ldsm4(bl[p * 2][0], bl[p * 2][1], bl[p * 2 + 1][0], bl[p * 2 + 1][1],
                      bA + p * (16 * P2 * 4) + SP * 4);
            }
            // pass 1: hi*hi -> acc
#pragma unroll
            for (int mi = 0; mi < 4; mi++)
#pragma unroll
                for (int ni = 0; ni < 4; ni++)
                    mma16(acc[mi][ni], ah[mi], bh[ni]);
            // pass 2: hi*lo -> acc2
#pragma unroll
            for (int mi = 0; mi < 4; mi++)
#pragma unroll
                for (int ni = 0; ni < 4; ni++)
                    mma16(acc2[mi][ni], ah[mi], bl[ni]);
            // pass 3: lo*hi -> acc2
#pragma unroll
            for (int mi = 0; mi < 4; mi++)
#pragma unroll
                for (int ni = 0; ni < 4; ni++)
                    mma16(acc2[mi][ni], al[mi], bh[ni]);
        }

        if (c + 2 < nk) stage_chunk(c + 2);
    }

    // epilogue: v = acc + acc2/2048 (+bias); optional stats / split-out / MSE
    float lsum = 0.f;
    float sc[4][2], ssc[4][2];
#pragma unroll
    for (int ni = 0; ni < 4; ni++) { sc[ni][0] = sc[ni][1] = 0.f; ssc[ni][0] = ssc[ni][1] = 0.f; }

#pragma unroll
    for (int mi = 0; mi < 4; mi++) {
#pragma unroll
        for (int h = 0; h < 2; h++) {
            const size_t m = (size_t)(m0 + wm * 64 + mi * 16 + (lane >> 2) + h * 8);
#pragma unroll
            for (int ni = 0; ni < 4; ni++) {
                const int col = n0 + wn * 32 + ni * 8 + 2 * (lane & 3);
                float v0 = acc[mi][ni][2 * h + 0] + acc2[mi][ni][2 * h + 0] * INV2048;
                float v1 = acc[mi][ni][2 * h + 1] + acc2[mi][ni][2 * h + 1] * INV2048;
                if (bias) { v0 += __ldg(bias + col); v1 += __ldg(bias + col + 1); }
                if (statSum) {
                    sc[ni][0] += v0; ssc[ni][0] += v0 * v0;
                    sc[ni][1] += v1; ssc[ni][1] += v1 * v1;
                }
                if (ref) {
                    float d0 = v0 - __ldg(ref + m * ldc + col);
                    float d1 = v1 - __ldg(ref + m * ldc + col + 1);
                    lsum += d0 * d0 + d1 * d1;
                }
                *(float2*)(C + m * ldc + col) = make_float2(v0, v1);
                if (CH) {
                    uint32_t hh, ll;
                    split2h(v0, v1, hh, ll);
                    size_t o2 = m * ldc2 + (size_t)(col >> 1);
                    CH[o2] = hh; CL[o2] = ll;
                }
            }
        }
    }
    if (statSum) {
#pragma unroll
        for (int ni = 0; ni < 4; ni++) {
            float s0 = sc[ni][0], s1 = sc[ni][1], q0 = ssc[ni][0], q1 = ssc[ni][1];
#pragma unroll
            for (int off = 4; off < 32; off <<= 1) {
                s0 += __shfl_down_sync(0xffffffffu, s0, off);
                s1 += __shfl_down_sync(0xffffffffu, s1, off);
                q0 += __shfl_down_sync(0xffffffffu, q0, off);
                q1 += __shfl_down_sync(0xffffffffu, q1, off);
            }
            if (lane < 4) {
                int col = n0 + wn * 32 + ni * 8 + 2 * lane;
                atomicAdd(&statSum[col],       s0);
                atomicAdd(&statSum[col + 1],   s1);
                atomicAdd(&statSumsq[col],     q0);
                atomicAdd(&statSumsq[col + 1], q1);
            }
        }
    }
    if (lossAcc) {
#pragma unroll
        for (int off = 16; off; off >>= 1)
            lsum += __shfl_down_sync(0xffffffffu, lsum, off);
        if (lane == 0) s_red[wid] = lsum;
        __syncthreads();
        if (tid == 0) {
            float s = 0.f;
#pragma unroll
            for (int w = 0; w < 8; w++) s += s_red[w];
            atomicAdd(lossAcc, s);
        }
    }
}

// ---------------- transpose ----------------
__global__ void transpose_kernel(const float* __restrict__ x, float* __restrict__ xt) {
    __shared__ float tile[32][33];
    int b  = blockIdx.z;
    int t0 = blockIdx.x * 32;
    int d0 = blockIdx.y * 32;
    int tx = threadIdx.x, ty = threadIdx.y;
    const float* xb = x  + (size_t)b * DIMV * TT;
    float*      xtb = xt + (size_t)b * TT * DIMV;
#pragma unroll
    for (int j = 0; j < 32; j += 8)
        tile[ty + j][tx] = xb[(size_t)(d0 + ty + j) * TT + t0 + tx];
    __syncthreads();
#pragma unroll
    for (int j = 0; j < 32; j += 8)
        xtb[(size_t)(t0 + ty + j) * DIMV + d0 + tx] = tile[tx][ty + j];
}

// ---------------- BN kernels ----------------
__global__ void colstats_kernel(const float* __restrict__ X, int N,
                                float* __restrict__ sum, float* __restrict__ sumsq) {
    int col = blockIdx.x * 32 + threadIdx.x;
    int r0  = blockIdx.y * 2048;
    float s = 0.f, ss = 0.f;
    for (int r = r0 + threadIdx.y; r < r0 + 2048; r += 8) {
        float v = X[(size_t)r * N + col];
        s += v; ss += v * v;
    }
    __shared__ float sh [8][32];
    __shared__ float sh2[8][32];
    sh [threadIdx.y][threadIdx.x] = s;
    sh2[threadIdx.y][threadIdx.x] = ss;
    __syncthreads();
    if (threadIdx.y == 0) {
#pragma unroll
        for (int w = 1; w < 8; w++) { s += sh[w][threadIdx.x]; ss += sh2[w][threadIdx.x]; }
        atomicAdd(&sum[col], s);
        atomicAdd(&sumsq[col], ss);
    }
}

__global__ void bnparams_kernel(const float* __restrict__ sum, const float* __restrict__ sumsq,
                                const float* __restrict__ g, const float* __restrict__ be, int N) {
    int c = blockIdx.x * 128 + threadIdx.x;
    if (c >= N) return;
    const float invM = 1.0f / (float)MROWS;
    float m   = sum[c] * invM;
    float var = sumsq[c] * invM - m * m;
    float sc  = g[c] * rsqrtf(var + 1e-5f);
    g_scale[c] = sc;
    g_shift[c] = be[c] - m * sc;
}

// apply BN (+relu) and emit split halves directly
__global__ void bnapply_split(const float* __restrict__ X,
                              uint32_t* __restrict__ H, uint32_t* __restrict__ L,
                              int mask, int relu) {
    size_t i = (size_t)blockIdx.x * 256 + threadIdx.x;
    float2 v = *(const float2*)(X + 2 * i);
    int c0 = (int)(2 * i) & mask;
    float a = v.x * g_scale[c0] + g_shift[c0];
    float b = v.y * g_scale[c0 + 1] + g_shift[c0 + 1];
    if (relu) { a = fmaxf(a, 0.f); b = fmaxf(b, 0.f); }
    uint32_t h, l;
    split2h(a, b, h, l);
    H[i] = h; L[i] = l;
}

// ---------------- gumbel ----------------
__device__ __forceinline__ float gumbel_of(float uu) {
    uu = fminf(fmaxf(uu, 1e-9f), 1.0f);
    return -logf(-logf(uu) + 1e-20f);
}

// ---------------- dual argmax with exact fp32 refinement ----------------
__global__ __launch_bounds__(256) void argmax_kernel(
    const float* __restrict__ logits, const float* __restrict__ z,
    const float* __restrict__ cb, const float* __restrict__ u,
    const float* __restrict__ lt, float* __restrict__ idx_out, int* __restrict__ code_out)
{
    const int q    = blockIdx.y;
    const int row  = blockIdx.x * 8 + (threadIdx.x >> 5);
    const int lane = threadIdx.x & 31;
    const float scale = expf(-__ldg(lt + q));
    const float* lrow = logits + ((size_t)q * MROWS + row) * CC;
    const float* urow = u + ((size_t)row * QQ + q) * CC;

    float lv[8], nn[8];
    bool exR[8], exN[8];
#pragma unroll
    for (int it = 0; it < 8; it++) {
        int c = it * 32 + lane;
        lv[it] = __ldg(lrow + c);
        nn[it] = lv[it] * scale + gumbel_of(__ldg(urow + c));
        exR[it] = false; exN[it] = false;
    }

    int candR[3], candN[3];
#pragma unroll
    for (int r = 0; r < 3; r++) {
        float bv = -INFINITY; int bi = 1 << 30;
#pragma unroll
        for (int it = 0; it < 8; it++)
            if (!exR[it] && (lv[it] > bv || (lv[it] == bv && it * 32 + lane < bi))) {
                bv = lv[it]; bi = it * 32 + lane;
            }
#pragma unroll
        for (int off = 16; off; off >>= 1) {
            float ov = __shfl_down_sync(0xffffffffu, bv, off);
            int   oi = __shfl_down_sync(0xffffffffu, bi, off);
            if (ov > bv || (ov == bv && oi < bi)) { bv = ov; bi = oi; }
        }
        bi = __shfl_sync(0xffffffffu, bi, 0);
        candR[r] = bi;
        if ((bi & 31) == lane) exR[bi >> 5] = true;

        bv = -INFINITY; bi = 1 << 30;
#pragma unroll
        for (int it = 0; it < 8; it++)
            if (!exN[it] && (nn[it] > bv || (nn[it] == bv && it * 32 + lane < bi))) {
                bv = nn[it]; bi = it * 32 + lane;
            }
#pragma unroll
        for (int off = 16; off; off >>= 1) {
            float ov = __shfl_down_sync(0xffffffffu, bv, off);
            int   oi = __shfl_down_sync(0xffffffffu, bi, off);
            if (ov > bv || (ov == bv && oi < bi)) { bv = ov; bi = oi; }
        }
        bi = __shfl_sync(0xffffffffu, bi, 0);
        candN[r] = bi;
        if ((bi & 31) == lane) exN[bi >> 5] = true;
    }

    const float* zrow = z + (size_t)row * (QQ * DD) + q * DD;
    float4 z0 = __ldg((const float4*)(zrow + lane * 8));
    float4 z1 = __ldg((const float4*)(zrow + lane * 8 + 4));
    float dR[3], dN[3];
#pragma unroll
    for (int r = 0; r < 3; r++) {
#pragma unroll
        for (int pass = 0; pass < 2; pass++) {
            int c = pass ? candN[r] : candR[r];
            const float* crow = cb + ((size_t)q * CC + c) * DD;
            float4 c0 = __ldg((const float4*)(crow + lane * 8));
            float4 c1 = __ldg((const float4*)(crow + lane * 8 + 4));
            float d = z0.x * c0.x + z0.y * c0.y + z0.z * c0.z + z0.w * c0.w
                    + z1.x * c1.x + z1.y * c1.y + z1.z * c1.z + z1.w * c1.w;
#pragma unroll
            for (int off = 16; off; off >>= 1)
                d += __shfl_down_sync(0xffffffffu, d, off);
            if (pass) dN[r] = d; else dR[r] = d;
        }
    }

    if (lane == 0) {
        int ri = candR[0]; float rv = dR[0];
#pragma unroll
        for (int r = 1; r < 3; r++)
            if (dR[r] > rv || (dR[r] == rv && candR[r] < ri)) { rv = dR[r]; ri = candR[r]; }
        int ni = candN[0];
        float nv = dN[0] * scale + gumbel_of(__ldg(urow + candN[0]));
#pragma unroll
        for (int r = 1; r < 3; r++) {
            float s = dN[r] * scale + gumbel_of(__ldg(urow + candN[r]));
            if (s > nv || (s == nv && candN[r] < ni)) { nv = s; ni = candN[r]; }
        }
        size_t o = (size_t)row * QQ + q;
        idx_out[o]  = (float)ri;
        code_out[o] = ni;
    }
}

// ---------------- embedding gather ----------------
__global__ void embed_kernel(const int* __restrict__ code, const float* __restrict__ cb,
                             float* __restrict__ emb) {
    int bt = blockIdx.x;
    int d  = threadIdx.x;
    float s = 0.f;
#pragma unroll
    for (int q = 0; q < QQ; q++) {
        int ci = code[bt * QQ + q];
        s += cb[((size_t)(q * CC + ci)) * DD + d];
    }
    emb[(size_t)bt * DD + d] = s;
}

__global__ void finalize_loss_kernel(float* __restrict__ out) {
    out[0] = g_loss[0] * (1.0f / (float)XR_N);
}

// ---------------- host orchestration ----------------
extern "C" void kernel_launch(void* const* d_in, const int* in_sizes, int n_in,
                              void* d_out, int out_size) {
    const float* x       = (const float*)d_in[0];
    const float* u       = (const float*)d_in[1];
    const float* cb      = (const float*)d_in[2];
    const float* lt      = (const float*)d_in[3];
    const float* enc_w0  = (const float*)d_in[4];
    const float* enc_b0  = (const float*)d_in[5];
    const float* enc_g0  = (const float*)d_in[6];
    const float* enc_be0 = (const float*)d_in[7];
    const float* enc_w1  = (const float*)d_in[8];
    const float* enc_b1  = (const float*)d_in[9];
    const float* enc_g1  = (const float*)d_in[10];
    const float* enc_be1 = (const float*)d_in[11];
    const float* enc_wo  = (const float*)d_in[12];
    const float* enc_bo  = (const float*)d_in[13];
    const float* dec_g   = (const float*)d_in[14];
    const float* dec_be  = (const float*)d_in[15];
    const float* dec_w0  = (const float*)d_in[16];
    const float* dec_b0  = (const float*)d_in[17];
    const float* dec_g0  = (const float*)d_in[18];
    const float* dec_be0 = (const float*)d_in[19];
    const float* dec_w1  = (const float*)d_in[20];
    const float* dec_b1  = (const float*)d_in[21];
    const float* dec_g1  = (const float*)d_in[22];
    const float* dec_be1 = (const float*)d_in[23];
    const float* fin_w   = (const float*)d_in[24];
    const float* fin_b   = (const float*)d_in[25];
    float* out = (float*)d_out;

    float *xt, *h0, *h1, *z, *logits, *emb, *sum, *sumsq, *loss;
    int* code;
    uint32_t *xtH, *xtL, *h0H, *h0L, *h1H, *h1L, *zH, *zL, *embH, *embL, *wH, *wL;
    cudaGetSymbolAddress((void**)&xt,    g_xt);
    cudaGetSymbolAddress((void**)&h0,    g_h0);
    cudaGetSymbolAddress((void**)&h1,    g_h1);
    cudaGetSymbolAddress((void**)&z,     g_z);
    cudaGetSymbolAddress((void**)&logits,g_logits);
    cudaGetSymbolAddress((void**)&emb,   g_emb);
    cudaGetSymbolAddress((void**)&code,  g_code);
    cudaGetSymbolAddress((void**)&sum,   g_sum);
    cudaGetSymbolAddress((void**)&sumsq, g_sumsq);
    cudaGetSymbolAddress((void**)&loss,  g_loss);
    cudaGetSymbolAddress((void**)&xtH,   g_xtH);   cudaGetSymbolAddress((void**)&xtL, g_xtL);
    cudaGetSymbolAddress((void**)&h0H,   g_h0H);   cudaGetSymbolAddress((void**)&h0L, g_h0L);
    cudaGetSymbolAddress((void**)&h1H,   g_h1H);   cudaGetSymbolAddress((void**)&h1L, g_h1L);
    cudaGetSymbolAddress((void**)&zH,    g_zH);    cudaGetSymbolAddress((void**)&zL,  g_zL);
    cudaGetSymbolAddress((void**)&embH,  g_embH);  cudaGetSymbolAddress((void**)&embL,g_embL);
    cudaGetSymbolAddress((void**)&wH,    g_wH);    cudaGetSymbolAddress((void**)&wL,  g_wL);

    cudaFuncSetAttribute(gemm_h, cudaFuncAttributeMaxDynamicSharedMemorySize, GSMEM2);

    // ---- pre-split weights + codebook ----
    split_mat<<<1024, 256>>>(enc_w0, wH + OFF_W0,  wL + OFF_W0);
    split_mat<<<2048, 256>>>(enc_w1, wH + OFF_W1,  wL + OFF_W1);
    split_mat<<<4096, 256>>>(enc_wo, wH + OFF_WO,  wL + OFF_WO);
    split_mat<<<1024, 256>>>(cb,     wH + OFF_CB,  wL + OFF_CB);
    split_mat<<< 512, 256>>>(dec_w0, wH + OFF_DW0, wL + OFF_DW0);
    split_mat<<<2048, 256>>>(dec_w1, wH + OFF_DW1, wL + OFF_DW1);
    split_mat<<<1024, 256>>>(fin_w,  wH + OFF_FW,  wL + OFF_FW);

    // ---- encoder ----
    transpose_kernel<<<dim3(TT / 32, DIMV / 32, BB), dim3(32, 8)>>>(x, xt);
    split_mat<<<16384, 256>>>(xt, xtH, xtL);

    cudaMemsetAsync(sum, 0, HIDV * sizeof(float));
    cudaMemsetAsync(sumsq, 0, HIDV * sizeof(float));
    gemm_h<<<dim3(HIDV / 128, MROWS / 128), 256, GSMEM2>>>(
        xtH, xtL, DIMV / 2, 0, wH + OFF_W0, wL + OFF_W0, DIMV / 2, 0,
        enc_b0, h0, HIDV, 0, nullptr, nullptr, 0, DIMV, sum, sumsq, nullptr, nullptr);
    bnparams_kernel<<<HIDV / 128, 128>>>(sum, sumsq, enc_g0, enc_be0, HIDV);
    bnapply_split<<<(unsigned)((size_t)MROWS * HIDV / 512), 256>>>(h0, h0H, h0L, HIDV - 1, 1);

    cudaMemsetAsync(sum, 0, HIDV * sizeof(float));
    cudaMemsetAsync(sumsq, 0, HIDV * sizeof(float));
    gemm_h<<<dim3(HIDV / 128, MROWS / 128), 256, GSMEM2>>>(
        h0H, h0L, HIDV / 2, 0, wH + OFF_W1, wL + OFF_W1, HIDV / 2, 0,
        enc_b1, h1, HIDV, 0, nullptr, nullptr, 0, HIDV, sum, sumsq, nullptr, nullptr);
    bnparams_kernel<<<HIDV / 128, 128>>>(sum, sumsq, enc_g1, enc_be1, HIDV);
    bnapply_split<<<(unsigned)((size_t)MROWS * HIDV / 512), 256>>>(h1, h1H, h1L, HIDV - 1, 1);

    // enc_wo: fp32 z + split halves out
    gemm_h<<<dim3((QQ * DD) / 128, MROWS / 128), 256, GSMEM2>>>(
        h1H, h1L, HIDV / 2, 0, wH + OFF_WO, wL + OFF_WO, HIDV / 2, 0,
        enc_bo, z, QQ * DD, 0, zH, zL, QQ * DD / 2, HIDV, nullptr, nullptr, nullptr, nullptr);

    // ---- logits (per-q block-diagonal) + argmax + embed ----
    gemm_h<<<dim3(CC / 128, MROWS / 128, QQ), 256, GSMEM2>>>(
        zH, zL, QQ * DD / 2, DD / 2,
        wH + OFF_CB, wL + OFF_CB, DD / 2, (long long)CC * DD / 2,
        nullptr, logits, CC, (long long)MROWS * CC,
        nullptr, nullptr, 0, DD, nullptr, nullptr, nullptr, nullptr);
    argmax_kernel<<<dim3(MROWS / 8, QQ), 256>>>(logits, z, cb, u, lt, out + XR_N, code);
    embed_kernel<<<MROWS, DD>>>(code, cb, emb);

    // ---- decoder ----
    cudaMemsetAsync(sum, 0, DD * sizeof(float));
    cudaMemsetAsync(sumsq, 0, DD * sizeof(float));
    colstats_kernel<<<dim3(DD / 32, 8), dim3(32, 8)>>>(emb, DD, sum, sumsq);
    bnparams_kernel<<<DD / 128, 128>>>(sum, sumsq, dec_g, dec_be, DD);
    bnapply_split<<<(unsigned)((size_t)MROWS * DD / 512), 256>>>(emb, embH, embL, DD - 1, 0);

    cudaMemsetAsync(sum, 0, HIDV * sizeof(float));
    cudaMemsetAsync(sumsq, 0, HIDV * sizeof(float));
    gemm_h<<<dim3(HIDV / 128, MROWS / 128), 256, GSMEM2>>>(
        embH, embL, DD / 2, 0, wH + OFF_DW0, wL + OFF_DW0, DD / 2, 0,
        dec_b0, h0, HIDV, 0, nullptr, nullptr, 0, DD, sum, sumsq, nullptr, nullptr);
    bnparams_kernel<<<HIDV / 128, 128>>>(sum, sumsq, dec_g0, dec_be0, HIDV);
    bnapply_split<<<(unsigned)((size_t)MROWS * HIDV / 512), 256>>>(h0, h0H, h0L, HIDV - 1, 1);

    cudaMemsetAsync(sum, 0, HIDV * sizeof(float));
    cudaMemsetAsync(sumsq, 0, HIDV * sizeof(float));
    gemm_h<<<dim3(HIDV / 128, MROWS / 128), 256, GSMEM2>>>(
        h0H, h0L, HIDV / 2, 0, wH + OFF_DW1, wL + OFF_DW1, HIDV / 2, 0,
        dec_b1, h1, HIDV, 0, nullptr, nullptr, 0, HIDV, sum, sumsq, nullptr, nullptr);
    bnparams_kernel<<<HIDV / 128, 128>>>(sum, sumsq, dec_g1, dec_be1, HIDV);
    bnapply_split<<<(unsigned)((size_t)MROWS * HIDV / 512), 256>>>(h1, h1H, h1L, HIDV - 1, 1);

    // ---- final linear + fused MSE loss vs xt ----
    cudaMemsetAsync(loss, 0, sizeof(float));
    gemm_h<<<dim3(DIMV / 128, MROWS / 128), 256, GSMEM2>>>(
        h1H, h1L, HIDV / 2, 0, wH + OFF_FW, wL + OFF_FW, HIDV / 2, 0,
        fin_b, out, DIMV, 0, nullptr, nullptr, 0, HIDV, nullptr, nullptr, xt, loss);
    finalize_loss_kernel<<<1, 1>>>(out + XR_N + IDX_N);
}